// round 8
// baseline (speedup 1.0000x reference)
#include <cuda_runtime.h>
#include <cuda_fp16.h>
#include <math.h>

#define NN 50000
#define EE 1600000
#define FDIM 128
#define NHEAD 4
#define SCAN_BS 256
#define SCAN_NB ((NN + SCAN_BS - 1) / SCAN_BS)   // 196

// ---------------- scratch (device globals, no allocation) ----------------
__device__ __half d_fth[NN * FDIM]; // transposed per-node features fp16: [n][d*4+h]
__device__ __half d_xh[NN * FDIM];  // inter-layer activations fp16: [n][h*32+d]
__device__ __half d_elh[NN * NHEAD];// attention left logits fp16 (packed half4)
__device__ float d_er[NN * NHEAD];
__device__ int   d_cnt[NN];
__device__ int   d_rowptr[NN + 1];
__device__ int   d_rowpos[NN];
__device__ int   d_esrc[EE];
__device__ int   d_scan_state[SCAN_NB];  // 0=invalid, 1=aggregate, 2=inclusive
__device__ int   d_scan_agg[SCAN_NB];
__device__ int   d_scan_incl[SCAN_NB];

// ---------------- CSR build ----------------
// int4-vectorized: 1 LDG.128 covers 4 edges -> 4x per-warp MLP
__global__ void count_kernel(const int4* __restrict__ dst4) {
    int i = blockIdx.x * blockDim.x + threadIdx.x;
    if (i < EE / 4) {
        int4 d = dst4[i];
        atomicAdd(&d_cnt[d.x], 1);
        atomicAdd(&d_cnt[d.y], 1);
        atomicAdd(&d_cnt[d.z], 1);
        atomicAdd(&d_cnt[d.w], 1);
    }
}

// single-pass exclusive scan of d_cnt -> d_rowptr/d_rowpos (decoupled lookback)
__global__ __launch_bounds__(SCAN_BS) void scan_lookback_kernel() {
    __shared__ int wagg[8];
    __shared__ int s_exc;
    int b = blockIdx.x, t = threadIdx.x;
    int lane = t & 31, wid = t >> 5;
    int i = b * SCAN_BS + t;
    int v = (i < NN) ? d_cnt[i] : 0;

    // block inclusive scan
    int x = v;
#pragma unroll
    for (int o = 1; o < 32; o <<= 1) {
        int y = __shfl_up_sync(0xffffffffu, x, o);
        if (lane >= o) x += y;
    }
    if (lane == 31) wagg[wid] = x;
    __syncthreads();
    if (t < 8) {
        int a = wagg[t];
#pragma unroll
        for (int o = 1; o < 8; o <<= 1) {
            int y = __shfl_up_sync(0xffu, a, o);
            if (t >= o) a += y;
        }
        wagg[t] = a;
    }
    __syncthreads();
    int incl = x + (wid > 0 ? wagg[wid - 1] : 0);
    int total = wagg[7];

    volatile int* vst = d_scan_state;
    volatile int* vagg = d_scan_agg;
    volatile int* vincl = d_scan_incl;
    if (t == 0) {
        if (b == 0) {
            d_scan_incl[0] = total;
            __threadfence();
            vst[0] = 2;
            s_exc = 0;
            d_rowptr[NN] = EE;
        } else {
            d_scan_agg[b] = total;
            __threadfence();
            vst[b] = 1;
            int sum = 0;
            int j = b - 1;
            while (1) {
                int st;
                while ((st = vst[j]) == 0) {}
                if (st == 2) { sum += vincl[j]; break; }
                sum += vagg[j];
                j--;
            }
            s_exc = sum;
            d_scan_incl[b] = sum + total;
            __threadfence();
            vst[b] = 2;
        }
    }
    __syncthreads();
    if (i < NN) {
        int off = s_exc + incl - v;   // exclusive prefix
        d_rowptr[i] = off;
        d_rowpos[i] = off;
    }
}

__global__ void scatter_kernel(const int4* __restrict__ src4, const int4* __restrict__ dst4) {
    int i = blockIdx.x * blockDim.x + threadIdx.x;
    if (i < EE / 4) {
        int4 s = src4[i];
        int4 d = dst4[i];
        int p0 = atomicAdd(&d_rowpos[d.x], 1);
        int p1 = atomicAdd(&d_rowpos[d.y], 1);
        int p2 = atomicAdd(&d_rowpos[d.z], 1);
        int p3 = atomicAdd(&d_rowpos[d.w], 1);
        d_esrc[p0] = s.x;
        d_esrc[p1] = s.y;
        d_esrc[p2] = s.z;
        d_esrc[p3] = s.w;
    }
}

// ---------------- tensor-core GEMM ----------------
__device__ __forceinline__ void mma16816(float* d,
                                         unsigned a0, unsigned a1, unsigned a2, unsigned a3,
                                         unsigned b0, unsigned b1) {
    asm volatile(
        "mma.sync.aligned.m16n8k16.row.col.f32.f16.f16.f32 "
        "{%0,%1,%2,%3}, {%4,%5,%6,%7}, {%8,%9}, {%0,%1,%2,%3};"
        : "+f"(d[0]), "+f"(d[1]), "+f"(d[2]), "+f"(d[3])
        : "r"(a0), "r"(a1), "r"(a2), "r"(a3), "r"(b0), "r"(b1));
}
__device__ __forceinline__ unsigned f2h2(float lo, float hi) {
    __half2 h = __floats2half2_rn(lo, hi);
    return *reinterpret_cast<unsigned*>(&h);
}

// ft = x @ W -> fp16 transposed [n][d*4+h], fused el/er, via HMMA m16n8k16.
// Block: 256 threads (8 warps), 128 rows/block, full N=128, K=128 (8 k-steps).
// X_IS_HALF: read activations from d_xh (fp16, no cvt); else from fp32 xin.
#define WSTRIDE 136
template <bool X_IS_HALF>
__global__ __launch_bounds__(256) void gemm_tc_kernel(const float* __restrict__ xin,
                                                      const float* __restrict__ W,
                                                      const float* __restrict__ al,
                                                      const float* __restrict__ ar) {
    __shared__ __half Wt[128 * WSTRIDE];   // union: W^T fp16 [n][k], then per-warp staging
    __shared__ float sal[128], sar[128];
    int t = threadIdx.x;
    int w = t >> 5, l = t & 31;
    int g = l >> 2, tig = l & 3;
    int row0 = blockIdx.x * 128;

    // W fp32 [k][n] -> Wt fp16 [n][k] (coalesced global read)
#pragma unroll
    for (int i = 0; i < 64; i++) {
        int idx = t + 256 * i;
        int k = idx >> 7, n = idx & 127;
        Wt[n * WSTRIDE + k] = __float2half(W[idx]);
    }
    if (t < 128) sal[t] = al[t];
    else sar[t - 128] = ar[t - 128];
    __syncthreads();

    float acc[16][4];
#pragma unroll
    for (int nt = 0; nt < 16; nt++)
#pragma unroll
        for (int j = 0; j < 4; j++) acc[nt][j] = 0.f;

    int r1 = row0 + w * 16 + g;   // rows this thread's fragments cover
    int r2 = r1 + 8;
    bool ok1 = r1 < NN, ok2 = r2 < NN;

#pragma unroll
    for (int ks = 0; ks < 8; ks++) {
        int k0 = ks * 16 + 2 * tig;
        unsigned a0 = 0, a1 = 0, a2 = 0, a3 = 0;
        if (X_IS_HALF) {
            if (ok1) {
                a0 = *reinterpret_cast<const unsigned*>(&d_xh[r1 * 128 + k0]);
                a2 = *reinterpret_cast<const unsigned*>(&d_xh[r1 * 128 + k0 + 8]);
            }
            if (ok2) {
                a1 = *reinterpret_cast<const unsigned*>(&d_xh[r2 * 128 + k0]);
                a3 = *reinterpret_cast<const unsigned*>(&d_xh[r2 * 128 + k0 + 8]);
            }
        } else {
            if (ok1) {
                float2 f = *reinterpret_cast<const float2*>(&xin[r1 * 128 + k0]);
                a0 = f2h2(f.x, f.y);
                f = *reinterpret_cast<const float2*>(&xin[r1 * 128 + k0 + 8]);
                a2 = f2h2(f.x, f.y);
            }
            if (ok2) {
                float2 f = *reinterpret_cast<const float2*>(&xin[r2 * 128 + k0]);
                a1 = f2h2(f.x, f.y);
                f = *reinterpret_cast<const float2*>(&xin[r2 * 128 + k0 + 8]);
                a3 = f2h2(f.x, f.y);
            }
        }
#pragma unroll
        for (int nt = 0; nt < 16; nt++) {
            const __half* bp = &Wt[(nt * 8 + g) * WSTRIDE + k0];
            unsigned b0 = *reinterpret_cast<const unsigned*>(bp);
            unsigned b1 = *reinterpret_cast<const unsigned*>(bp + 8);
            mma16816(acc[nt], a0, a1, a2, a3, b0, b1);
        }
    }

    // fused el/er from fragments: col c = nt*8 + 2*tig (+1); head = nt>>2
    {
        float pll[4] = {0, 0, 0, 0}, plh[4] = {0, 0, 0, 0};
        float prl[4] = {0, 0, 0, 0}, prh[4] = {0, 0, 0, 0};
#pragma unroll
        for (int nt = 0; nt < 16; nt++) {
            int hh = nt >> 2;
            int c = nt * 8 + 2 * tig;
            float s0 = sal[c], s1 = sal[c + 1];
            float u0 = sar[c], u1 = sar[c + 1];
            pll[hh] += acc[nt][0] * s0 + acc[nt][1] * s1;
            plh[hh] += acc[nt][2] * s0 + acc[nt][3] * s1;
            prl[hh] += acc[nt][0] * u0 + acc[nt][1] * u1;
            prh[hh] += acc[nt][2] * u0 + acc[nt][3] * u1;
        }
#pragma unroll
        for (int o = 1; o <= 2; o <<= 1) {
#pragma unroll
            for (int hh = 0; hh < 4; hh++) {
                pll[hh] += __shfl_xor_sync(0xffffffffu, pll[hh], o);
                plh[hh] += __shfl_xor_sync(0xffffffffu, plh[hh], o);
                prl[hh] += __shfl_xor_sync(0xffffffffu, prl[hh], o);
                prh[hh] += __shfl_xor_sync(0xffffffffu, prh[hh], o);
            }
        }
        if (tig == 0) {
            if (ok1) {
                uint2 e;
                e.x = f2h2(pll[0], pll[1]);
                e.y = f2h2(pll[2], pll[3]);
                *reinterpret_cast<uint2*>(&d_elh[r1 * 4]) = e;
                *reinterpret_cast<float4*>(&d_er[r1 * 4]) = make_float4(prl[0], prl[1], prl[2], prl[3]);
            }
            if (ok2) {
                uint2 e;
                e.x = f2h2(plh[0], plh[1]);
                e.y = f2h2(plh[2], plh[3]);
                *reinterpret_cast<uint2*>(&d_elh[r2 * 4]) = e;
                *reinterpret_cast<float4*>(&d_er[r2 * 4]) = make_float4(prh[0], prh[1], prh[2], prh[3]);
            }
        }
    }

    // stage D (fp16) per warp, then write ft transposed [r][d*4+h]
    __syncthreads();   // all warps done reading Wt
    __half* stg = &Wt[w * 16 * WSTRIDE];
#pragma unroll
    for (int nt = 0; nt < 16; nt++) {
        int c = nt * 8 + 2 * tig;
        *reinterpret_cast<unsigned*>(&stg[g * WSTRIDE + c]) = f2h2(acc[nt][0], acc[nt][1]);
        *reinterpret_cast<unsigned*>(&stg[(g + 8) * WSTRIDE + c]) = f2h2(acc[nt][2], acc[nt][3]);
    }
    __syncwarp();
#pragma unroll
    for (int r = 0; r < 16; r++) {
        int rr = row0 + w * 16 + r;
        if (rr < NN) {
            __half v0 = stg[r * WSTRIDE + l];
            __half v1 = stg[r * WSTRIDE + 32 + l];
            __half v2 = stg[r * WSTRIDE + 64 + l];
            __half v3 = stg[r * WSTRIDE + 96 + l];
            __half2 p01 = __halves2half2(v0, v1);
            __half2 p23 = __halves2half2(v2, v3);
            uint2 o;
            o.x = *reinterpret_cast<unsigned*>(&p01);
            o.y = *reinterpret_cast<unsigned*>(&p23);
            *reinterpret_cast<uint2*>(&d_fth[rr * 128 + l * 4]) = o;
        }
    }
}

// ---------------- per-dst-node softmax + aggregation, single pass (no max) ----------------
// Softmax is shift-invariant; |e| is O(1) here so exp() cannot overflow fp32.
// MODE 0: write ELU(result) as fp16 into d_xh ([n][h*32+d]). MODE 1: write mean over heads into out.
template <int MODE>
__global__ __launch_bounds__(256) void agg_kernel(const float* __restrict__ bias,
                                                  float* __restrict__ out) {
    __shared__ float4 sw[8][32];
    __shared__ int ss[8][32];
    int warp = threadIdx.x >> 5, lane = threadIdx.x & 31;
    int n = blockIdx.x * 8 + warp;
    if (n >= NN) return;
    int start = d_rowptr[n], end = d_rowptr[n + 1];
    float4 ern = *reinterpret_cast<const float4*>(&d_er[n * 4]);

    float acc0 = 0.f, acc1 = 0.f, acc2 = 0.f, acc3 = 0.f;
    float z0 = 0.f, z1 = 0.f, z2 = 0.f, z3 = 0.f;

    for (int c = start; c < end; c += 32) {
        int idx = c + lane;
        int s = 0;
        float4 w = make_float4(0.f, 0.f, 0.f, 0.f);
        if (idx < end) {
            s = d_esrc[idx];
            uint2 eh = *reinterpret_cast<const uint2*>(&d_elh[s * 4]);
            float2 e01 = __half22float2(*reinterpret_cast<__half2*>(&eh.x));
            float2 e23 = __half22float2(*reinterpret_cast<__half2*>(&eh.y));
            float e;
            e = e01.x + ern.x; e = e > 0.f ? e : 0.2f * e; w.x = __expf(e);
            e = e01.y + ern.y; e = e > 0.f ? e : 0.2f * e; w.y = __expf(e);
            e = e23.x + ern.z; e = e > 0.f ? e : 0.2f * e; w.z = __expf(e);
            e = e23.y + ern.w; e = e > 0.f ? e : 0.2f * e; w.w = __expf(e);
            z0 += w.x; z1 += w.y; z2 += w.z; z3 += w.w;
        }
        ss[warp][lane] = s;
        sw[warp][lane] = w;
        __syncwarp();
        int cnt = end - c; if (cnt > 32) cnt = 32;
        int j = 0;
        // 4-wide batches: 4 independent LDG.64 in flight before the FMAs
        for (; j + 4 <= cnt; j += 4) {
            int sa = ss[warp][j], sb = ss[warp][j + 1];
            int sc = ss[warp][j + 2], sd = ss[warp][j + 3];
            float4 wa = sw[warp][j], wb = sw[warp][j + 1];
            float4 wc = sw[warp][j + 2], wd = sw[warp][j + 3];
            uint2 fa = *reinterpret_cast<const uint2*>(&d_fth[sa * 128 + lane * 4]);
            uint2 fb = *reinterpret_cast<const uint2*>(&d_fth[sb * 128 + lane * 4]);
            uint2 fc = *reinterpret_cast<const uint2*>(&d_fth[sc * 128 + lane * 4]);
            uint2 fd = *reinterpret_cast<const uint2*>(&d_fth[sd * 128 + lane * 4]);
            float2 a01 = __half22float2(*reinterpret_cast<__half2*>(&fa.x));
            float2 a23 = __half22float2(*reinterpret_cast<__half2*>(&fa.y));
            float2 b01 = __half22float2(*reinterpret_cast<__half2*>(&fb.x));
            float2 b23 = __half22float2(*reinterpret_cast<__half2*>(&fb.y));
            float2 c01 = __half22float2(*reinterpret_cast<__half2*>(&fc.x));
            float2 c23 = __half22float2(*reinterpret_cast<__half2*>(&fc.y));
            float2 d01 = __half22float2(*reinterpret_cast<__half2*>(&fd.x));
            float2 d23 = __half22float2(*reinterpret_cast<__half2*>(&fd.y));
            acc0 += wa.x * a01.x; acc1 += wa.y * a01.y; acc2 += wa.z * a23.x; acc3 += wa.w * a23.y;
            acc0 += wb.x * b01.x; acc1 += wb.y * b01.y; acc2 += wb.z * b23.x; acc3 += wb.w * b23.y;
            acc0 += wc.x * c01.x; acc1 += wc.y * c01.y; acc2 += wc.z * c23.x; acc3 += wc.w * c23.y;
            acc0 += wd.x * d01.x; acc1 += wd.y * d01.y; acc2 += wd.z * d23.x; acc3 += wd.w * d23.y;
        }
        for (; j < cnt; j++) {
            int s2 = ss[warp][j];
            float4 wv = sw[warp][j];
            uint2 f = *reinterpret_cast<const uint2*>(&d_fth[s2 * 128 + lane * 4]);
            float2 f01 = __half22float2(*reinterpret_cast<__half2*>(&f.x));
            float2 f23 = __half22float2(*reinterpret_cast<__half2*>(&f.y));
            acc0 += wv.x * f01.x; acc1 += wv.y * f01.y;
            acc2 += wv.z * f23.x; acc3 += wv.w * f23.y;
        }
        __syncwarp();
    }
#pragma unroll
    for (int o = 16; o > 0; o >>= 1) {
        z0 += __shfl_xor_sync(0xffffffffu, z0, o);
        z1 += __shfl_xor_sync(0xffffffffu, z1, o);
        z2 += __shfl_xor_sync(0xffffffffu, z2, o);
        z3 += __shfl_xor_sync(0xffffffffu, z3, o);
    }

    float v0 = (z0 > 0.f ? acc0 / z0 : 0.f) + bias[0 * 32 + lane];
    float v1 = (z1 > 0.f ? acc1 / z1 : 0.f) + bias[1 * 32 + lane];
    float v2 = (z2 > 0.f ? acc2 / z2 : 0.f) + bias[2 * 32 + lane];
    float v3 = (z3 > 0.f ? acc3 / z3 : 0.f) + bias[3 * 32 + lane];

    if (MODE == 0) {
        v0 = v0 > 0.f ? v0 : __expf(v0) - 1.f;
        v1 = v1 > 0.f ? v1 : __expf(v1) - 1.f;
        v2 = v2 > 0.f ? v2 : __expf(v2) - 1.f;
        v3 = v3 > 0.f ? v3 : __expf(v3) - 1.f;
        d_xh[n * 128 + 0 * 32 + lane] = __float2half(v0);
        d_xh[n * 128 + 1 * 32 + lane] = __float2half(v1);
        d_xh[n * 128 + 2 * 32 + lane] = __float2half(v2);
        d_xh[n * 128 + 3 * 32 + lane] = __float2half(v3);
    } else {
        out[n * 32 + lane] = (v0 + v1 + v2 + v3) * 0.25f;
    }
}

// ---------------- launch ----------------
extern "C" void kernel_launch(void* const* d_in, const int* in_sizes, int n_in,
                              void* d_out, int out_size) {
    const float* h   = (const float*)d_in[0];
    const int*   src = (const int*)d_in[1];
    const int*   dst = (const int*)d_in[2];
    const float* W1  = (const float*)d_in[3];
    const float* al1 = (const float*)d_in[4];
    const float* ar1 = (const float*)d_in[5];
    const float* b1  = (const float*)d_in[6];
    const float* W2  = (const float*)d_in[7];
    const float* al2 = (const float*)d_in[8];
    const float* ar2 = (const float*)d_in[9];
    const float* b2  = (const float*)d_in[10];
    const float* W3  = (const float*)d_in[11];
    const float* al3 = (const float*)d_in[12];
    const float* ar3 = (const float*)d_in[13];
    const float* b3  = (const float*)d_in[14];
    float* out = (float*)d_out;

    const int GEMM_BLOCKS = (NN + 127) / 128;
    const int NODE_BLOCKS = (NN + 7) / 8;
    const int E4_BLOCKS = (EE / 4 + 255) / 256;

    // zero cnt + scan state via capturable async memsets
    void* p_cnt = nullptr;
    void* p_state = nullptr;
    cudaGetSymbolAddress(&p_cnt, d_cnt);
    cudaGetSymbolAddress(&p_state, d_scan_state);
    cudaMemsetAsync(p_cnt, 0, NN * sizeof(int));
    cudaMemsetAsync(p_state, 0, SCAN_NB * sizeof(int));

    // CSR build (reused by all 3 layers)
    count_kernel<<<E4_BLOCKS, 256>>>((const int4*)dst);
    scan_lookback_kernel<<<SCAN_NB, SCAN_BS>>>();
    scatter_kernel<<<E4_BLOCKS, 256>>>((const int4*)src, (const int4*)dst);

    // layer 1
    gemm_tc_kernel<false><<<GEMM_BLOCKS, 256>>>(h, W1, al1, ar1);
    agg_kernel<0><<<NODE_BLOCKS, 256>>>(b1, nullptr);

    // layer 2
    gemm_tc_kernel<true><<<GEMM_BLOCKS, 256>>>(nullptr, W2, al2, ar2);
    agg_kernel<0><<<NODE_BLOCKS, 256>>>(b2, nullptr);

    // layer 3
    gemm_tc_kernel<true><<<GEMM_BLOCKS, 256>>>(nullptr, W3, al3, ar3);
    agg_kernel<1><<<NODE_BLOCKS, 256>>>(b3, out);
}

// round 9
// speedup vs baseline: 1.0636x; 1.0636x over previous
#include <cuda_runtime.h>
#include <cuda_fp16.h>
#include <math.h>

#define NN 50000
#define EE 1600000
#define FDIM 128
#define NHEAD 4
#define SCAN_BS 256
#define SCAN_NB ((NN + SCAN_BS - 1) / SCAN_BS)   // 196

// ---------------- scratch (device globals, no allocation) ----------------
__device__ __half d_fth[NN * FDIM]; // transposed per-node features fp16: [n][d*4+h]
__device__ __half d_xh[NN * FDIM];  // inter-layer activations fp16: [n][h*32+d]
__device__ float d_el[NN * NHEAD];
__device__ float d_er[NN * NHEAD];
__device__ int   d_cnt[NN];
__device__ int   d_rowptr[NN + 1];
__device__ int   d_rowpos[NN];
__device__ int   d_esrc[EE];
__device__ int   d_bsum[SCAN_NB];
__device__ int   d_boff[SCAN_NB];

// ---------------- CSR build ----------------
// int4-vectorized: 1 LDG.128 covers 4 edges -> 4x per-warp MLP
__global__ void count_kernel(const int4* __restrict__ dst4) {
    int i = blockIdx.x * blockDim.x + threadIdx.x;
    if (i < EE / 4) {
        int4 d = dst4[i];
        atomicAdd(&d_cnt[d.x], 1);
        atomicAdd(&d_cnt[d.y], 1);
        atomicAdd(&d_cnt[d.z], 1);
        atomicAdd(&d_cnt[d.w], 1);
    }
}

// phase A: per-block sums of cnt
__global__ __launch_bounds__(SCAN_BS) void csr_blocksum_kernel() {
    __shared__ int sh[SCAN_BS];
    int i = blockIdx.x * SCAN_BS + threadIdx.x;
    int v = (i < NN) ? d_cnt[i] : 0;
    sh[threadIdx.x] = v;
    __syncthreads();
    for (int d = SCAN_BS / 2; d > 0; d >>= 1) {
        if (threadIdx.x < d) sh[threadIdx.x] += sh[threadIdx.x + d];
        __syncthreads();
    }
    if (threadIdx.x == 0) d_bsum[blockIdx.x] = sh[0];
}

// phase B: exclusive scan of block sums (single small block)
__global__ __launch_bounds__(SCAN_BS) void csr_scanb_kernel() {
    __shared__ int sh[SCAN_BS];
    int t = threadIdx.x;
    int v = (t < SCAN_NB) ? d_bsum[t] : 0;
    sh[t] = v;
    __syncthreads();
    for (int d = 1; d < SCAN_BS; d <<= 1) {
        int x = sh[t];
        int add = (t >= d) ? sh[t - d] : 0;
        __syncthreads();
        sh[t] = x + add;
        __syncthreads();
    }
    if (t < SCAN_NB) d_boff[t] = sh[t] - v;   // exclusive
    if (t == SCAN_NB - 1) d_rowptr[NN] = sh[t];
}

// phase C: block-local exclusive scan + global offset -> rowptr/rowpos
__global__ __launch_bounds__(SCAN_BS) void csr_emit_kernel() {
    __shared__ int sh[SCAN_BS];
    int t = threadIdx.x;
    int i = blockIdx.x * SCAN_BS + t;
    int v = (i < NN) ? d_cnt[i] : 0;
    sh[t] = v;
    __syncthreads();
    for (int d = 1; d < SCAN_BS; d <<= 1) {
        int x = sh[t];
        int add = (t >= d) ? sh[t - d] : 0;
        __syncthreads();
        sh[t] = x + add;
        __syncthreads();
    }
    if (i < NN) {
        int off = d_boff[blockIdx.x] + sh[t] - v;   // exclusive prefix
        d_rowptr[i] = off;
        d_rowpos[i] = off;
    }
}

__global__ void scatter_kernel(const int4* __restrict__ src4, const int4* __restrict__ dst4) {
    int i = blockIdx.x * blockDim.x + threadIdx.x;
    if (i < EE / 4) {
        int4 s = src4[i];
        int4 d = dst4[i];
        int p0 = atomicAdd(&d_rowpos[d.x], 1);
        int p1 = atomicAdd(&d_rowpos[d.y], 1);
        int p2 = atomicAdd(&d_rowpos[d.z], 1);
        int p3 = atomicAdd(&d_rowpos[d.w], 1);
        d_esrc[p0] = s.x;
        d_esrc[p1] = s.y;
        d_esrc[p2] = s.z;
        d_esrc[p3] = s.w;
    }
}

// ---------------- tensor-core GEMM ----------------
__device__ __forceinline__ void mma16816(float* d,
                                         unsigned a0, unsigned a1, unsigned a2, unsigned a3,
                                         unsigned b0, unsigned b1) {
    asm volatile(
        "mma.sync.aligned.m16n8k16.row.col.f32.f16.f16.f32 "
        "{%0,%1,%2,%3}, {%4,%5,%6,%7}, {%8,%9}, {%0,%1,%2,%3};"
        : "+f"(d[0]), "+f"(d[1]), "+f"(d[2]), "+f"(d[3])
        : "r"(a0), "r"(a1), "r"(a2), "r"(a3), "r"(b0), "r"(b1));
}
__device__ __forceinline__ unsigned f2h2(float lo, float hi) {
    __half2 h = __floats2half2_rn(lo, hi);
    return *reinterpret_cast<unsigned*>(&h);
}

// ft = x @ W -> fp16 transposed [n][d*4+h], fused el/er (fp32), via HMMA m16n8k16.
// Block: 256 threads (8 warps), 128 rows/block, full N=128, K=128 (8 k-steps).
// __launch_bounds__(256, 2): cap regs at 128 so 2 CTAs fit per SM (was 1 -> latency-bound).
#define WSTRIDE 136
template <bool X_IS_HALF>
__global__ __launch_bounds__(256, 2) void gemm_tc_kernel(const float* __restrict__ xin,
                                                         const float* __restrict__ W,
                                                         const float* __restrict__ al,
                                                         const float* __restrict__ ar) {
    __shared__ __half Wt[128 * WSTRIDE];   // union: W^T fp16 [n][k], then per-warp staging
    __shared__ float sal[128], sar[128];
    int t = threadIdx.x;
    int w = t >> 5, l = t & 31;
    int g = l >> 2, tig = l & 3;
    int row0 = blockIdx.x * 128;

    // W fp32 [k][n] -> Wt fp16 [n][k] (coalesced global read)
#pragma unroll
    for (int i = 0; i < 64; i++) {
        int idx = t + 256 * i;
        int k = idx >> 7, n = idx & 127;
        Wt[n * WSTRIDE + k] = __float2half(W[idx]);
    }
    if (t < 128) sal[t] = al[t];
    else sar[t - 128] = ar[t - 128];
    __syncthreads();

    float acc[16][4];
#pragma unroll
    for (int nt = 0; nt < 16; nt++)
#pragma unroll
        for (int j = 0; j < 4; j++) acc[nt][j] = 0.f;

    int r1 = row0 + w * 16 + g;   // rows this thread's fragments cover
    int r2 = r1 + 8;
    bool ok1 = r1 < NN, ok2 = r2 < NN;

#pragma unroll
    for (int ks = 0; ks < 8; ks++) {
        int k0 = ks * 16 + 2 * tig;
        unsigned a0 = 0, a1 = 0, a2 = 0, a3 = 0;
        if (X_IS_HALF) {
            if (ok1) {
                a0 = *reinterpret_cast<const unsigned*>(&d_xh[r1 * 128 + k0]);
                a2 = *reinterpret_cast<const unsigned*>(&d_xh[r1 * 128 + k0 + 8]);
            }
            if (ok2) {
                a1 = *reinterpret_cast<const unsigned*>(&d_xh[r2 * 128 + k0]);
                a3 = *reinterpret_cast<const unsigned*>(&d_xh[r2 * 128 + k0 + 8]);
            }
        } else {
            if (ok1) {
                float2 f = *reinterpret_cast<const float2*>(&xin[r1 * 128 + k0]);
                a0 = f2h2(f.x, f.y);
                f = *reinterpret_cast<const float2*>(&xin[r1 * 128 + k0 + 8]);
                a2 = f2h2(f.x, f.y);
            }
            if (ok2) {
                float2 f = *reinterpret_cast<const float2*>(&xin[r2 * 128 + k0]);
                a1 = f2h2(f.x, f.y);
                f = *reinterpret_cast<const float2*>(&xin[r2 * 128 + k0 + 8]);
                a3 = f2h2(f.x, f.y);
            }
        }
#pragma unroll
        for (int nt = 0; nt < 16; nt++) {
            const __half* bp = &Wt[(nt * 8 + g) * WSTRIDE + k0];
            unsigned b0 = *reinterpret_cast<const unsigned*>(bp);
            unsigned b1 = *reinterpret_cast<const unsigned*>(bp + 8);
            mma16816(acc[nt], a0, a1, a2, a3, b0, b1);
        }
    }

    // fused el/er from fragments: col c = nt*8 + 2*tig (+1); head = nt>>2
    {
        float pll[4] = {0, 0, 0, 0}, plh[4] = {0, 0, 0, 0};
        float prl[4] = {0, 0, 0, 0}, prh[4] = {0, 0, 0, 0};
#pragma unroll
        for (int nt = 0; nt < 16; nt++) {
            int hh = nt >> 2;
            int c = nt * 8 + 2 * tig;
            float s0 = sal[c], s1 = sal[c + 1];
            float u0 = sar[c], u1 = sar[c + 1];
            pll[hh] += acc[nt][0] * s0 + acc[nt][1] * s1;
            plh[hh] += acc[nt][2] * s0 + acc[nt][3] * s1;
            prl[hh] += acc[nt][0] * u0 + acc[nt][1] * u1;
            prh[hh] += acc[nt][2] * u0 + acc[nt][3] * u1;
        }
#pragma unroll
        for (int o = 1; o <= 2; o <<= 1) {
#pragma unroll
            for (int hh = 0; hh < 4; hh++) {
                pll[hh] += __shfl_xor_sync(0xffffffffu, pll[hh], o);
                plh[hh] += __shfl_xor_sync(0xffffffffu, plh[hh], o);
                prl[hh] += __shfl_xor_sync(0xffffffffu, prl[hh], o);
                prh[hh] += __shfl_xor_sync(0xffffffffu, prh[hh], o);
            }
        }
        if (tig == 0) {
            if (ok1) {
                *reinterpret_cast<float4*>(&d_el[r1 * 4]) = make_float4(pll[0], pll[1], pll[2], pll[3]);
                *reinterpret_cast<float4*>(&d_er[r1 * 4]) = make_float4(prl[0], prl[1], prl[2], prl[3]);
            }
            if (ok2) {
                *reinterpret_cast<float4*>(&d_el[r2 * 4]) = make_float4(plh[0], plh[1], plh[2], plh[3]);
                *reinterpret_cast<float4*>(&d_er[r2 * 4]) = make_float4(prh[0], prh[1], prh[2], prh[3]);
            }
        }
    }

    // stage D (fp16) per warp, then write ft transposed [r][d*4+h]
    __syncthreads();   // all warps done reading Wt
    __half* stg = &Wt[w * 16 * WSTRIDE];
#pragma unroll
    for (int nt = 0; nt < 16; nt++) {
        int c = nt * 8 + 2 * tig;
        *reinterpret_cast<unsigned*>(&stg[g * WSTRIDE + c]) = f2h2(acc[nt][0], acc[nt][1]);
        *reinterpret_cast<unsigned*>(&stg[(g + 8) * WSTRIDE + c]) = f2h2(acc[nt][2], acc[nt][3]);
    }
    __syncwarp();
#pragma unroll
    for (int r = 0; r < 16; r++) {
        int rr = row0 + w * 16 + r;
        if (rr < NN) {
            __half v0 = stg[r * WSTRIDE + l];
            __half v1 = stg[r * WSTRIDE + 32 + l];
            __half v2 = stg[r * WSTRIDE + 64 + l];
            __half v3 = stg[r * WSTRIDE + 96 + l];
            __half2 p01 = __halves2half2(v0, v1);
            __half2 p23 = __halves2half2(v2, v3);
            uint2 o;
            o.x = *reinterpret_cast<unsigned*>(&p01);
            o.y = *reinterpret_cast<unsigned*>(&p23);
            *reinterpret_cast<uint2*>(&d_fth[rr * 128 + l * 4]) = o;
        }
    }
}

// ---------------- per-dst-node softmax + aggregation, single pass (no max) ----------------
// Softmax is shift-invariant; |e| is O(1) here so exp() cannot overflow fp32.
// MODE 0: write ELU(result) as fp16 into d_xh ([n][h*32+d]). MODE 1: write mean over heads into out.
template <int MODE>
__global__ __launch_bounds__(256) void agg_kernel(const float* __restrict__ bias,
                                                  float* __restrict__ out) {
    __shared__ float4 sw[8][32];
    __shared__ int ss[8][32];
    int warp = threadIdx.x >> 5, lane = threadIdx.x & 31;
    int n = blockIdx.x * 8 + warp;
    if (n >= NN) return;
    int start = d_rowptr[n], end = d_rowptr[n + 1];
    float4 ern = *reinterpret_cast<const float4*>(&d_er[n * 4]);

    float acc0 = 0.f, acc1 = 0.f, acc2 = 0.f, acc3 = 0.f;
    float z0 = 0.f, z1 = 0.f, z2 = 0.f, z3 = 0.f;

    for (int c = start; c < end; c += 32) {
        int idx = c + lane;
        int s = 0;
        float4 w = make_float4(0.f, 0.f, 0.f, 0.f);
        if (idx < end) {
            s = d_esrc[idx];
            float4 e4 = *reinterpret_cast<const float4*>(&d_el[s * 4]);
            float e;
            e = e4.x + ern.x; e = e > 0.f ? e : 0.2f * e; w.x = __expf(e);
            e = e4.y + ern.y; e = e > 0.f ? e : 0.2f * e; w.y = __expf(e);
            e = e4.z + ern.z; e = e > 0.f ? e : 0.2f * e; w.z = __expf(e);
            e = e4.w + ern.w; e = e > 0.f ? e : 0.2f * e; w.w = __expf(e);
            z0 += w.x; z1 += w.y; z2 += w.z; z3 += w.w;
        }
        ss[warp][lane] = s;
        sw[warp][lane] = w;
        __syncwarp();
        int cnt = end - c; if (cnt > 32) cnt = 32;
        int j = 0;
        // 4-wide batches: 4 independent LDG.64 in flight before the FMAs
        for (; j + 4 <= cnt; j += 4) {
            int sa = ss[warp][j], sb = ss[warp][j + 1];
            int sc = ss[warp][j + 2], sd = ss[warp][j + 3];
            float4 wa = sw[warp][j], wb = sw[warp][j + 1];
            float4 wc = sw[warp][j + 2], wd = sw[warp][j + 3];
            uint2 fa = *reinterpret_cast<const uint2*>(&d_fth[sa * 128 + lane * 4]);
            uint2 fb = *reinterpret_cast<const uint2*>(&d_fth[sb * 128 + lane * 4]);
            uint2 fc = *reinterpret_cast<const uint2*>(&d_fth[sc * 128 + lane * 4]);
            uint2 fd = *reinterpret_cast<const uint2*>(&d_fth[sd * 128 + lane * 4]);
            float2 a01 = __half22float2(*reinterpret_cast<__half2*>(&fa.x));
            float2 a23 = __half22float2(*reinterpret_cast<__half2*>(&fa.y));
            float2 b01 = __half22float2(*reinterpret_cast<__half2*>(&fb.x));
            float2 b23 = __half22float2(*reinterpret_cast<__half2*>(&fb.y));
            float2 c01 = __half22float2(*reinterpret_cast<__half2*>(&fc.x));
            float2 c23 = __half22float2(*reinterpret_cast<__half2*>(&fc.y));
            float2 d01 = __half22float2(*reinterpret_cast<__half2*>(&fd.x));
            float2 d23 = __half22float2(*reinterpret_cast<__half2*>(&fd.y));
            acc0 += wa.x * a01.x; acc1 += wa.y * a01.y; acc2 += wa.z * a23.x; acc3 += wa.w * a23.y;
            acc0 += wb.x * b01.x; acc1 += wb.y * b01.y; acc2 += wb.z * b23.x; acc3 += wb.w * b23.y;
            acc0 += wc.x * c01.x; acc1 += wc.y * c01.y; acc2 += wc.z * c23.x; acc3 += wc.w * c23.y;
            acc0 += wd.x * d01.x; acc1 += wd.y * d01.y; acc2 += wd.z * d23.x; acc3 += wd.w * d23.y;
        }
        for (; j < cnt; j++) {
            int s2 = ss[warp][j];
            float4 wv = sw[warp][j];
            uint2 f = *reinterpret_cast<const uint2*>(&d_fth[s2 * 128 + lane * 4]);
            float2 f01 = __half22float2(*reinterpret_cast<__half2*>(&f.x));
            float2 f23 = __half22float2(*reinterpret_cast<__half2*>(&f.y));
            acc0 += wv.x * f01.x; acc1 += wv.y * f01.y;
            acc2 += wv.z * f23.x; acc3 += wv.w * f23.y;
        }
        __syncwarp();
    }
#pragma unroll
    for (int o = 16; o > 0; o >>= 1) {
        z0 += __shfl_xor_sync(0xffffffffu, z0, o);
        z1 += __shfl_xor_sync(0xffffffffu, z1, o);
        z2 += __shfl_xor_sync(0xffffffffu, z2, o);
        z3 += __shfl_xor_sync(0xffffffffu, z3, o);
    }

    float v0 = (z0 > 0.f ? acc0 / z0 : 0.f) + bias[0 * 32 + lane];
    float v1 = (z1 > 0.f ? acc1 / z1 : 0.f) + bias[1 * 32 + lane];
    float v2 = (z2 > 0.f ? acc2 / z2 : 0.f) + bias[2 * 32 + lane];
    float v3 = (z3 > 0.f ? acc3 / z3 : 0.f) + bias[3 * 32 + lane];

    if (MODE == 0) {
        v0 = v0 > 0.f ? v0 : __expf(v0) - 1.f;
        v1 = v1 > 0.f ? v1 : __expf(v1) - 1.f;
        v2 = v2 > 0.f ? v2 : __expf(v2) - 1.f;
        v3 = v3 > 0.f ? v3 : __expf(v3) - 1.f;
        d_xh[n * 128 + 0 * 32 + lane] = __float2half(v0);
        d_xh[n * 128 + 1 * 32 + lane] = __float2half(v1);
        d_xh[n * 128 + 2 * 32 + lane] = __float2half(v2);
        d_xh[n * 128 + 3 * 32 + lane] = __float2half(v3);
    } else {
        out[n * 32 + lane] = (v0 + v1 + v2 + v3) * 0.25f;
    }
}

// ---------------- launch ----------------
extern "C" void kernel_launch(void* const* d_in, const int* in_sizes, int n_in,
                              void* d_out, int out_size) {
    const float* h   = (const float*)d_in[0];
    const int*   src = (const int*)d_in[1];
    const int*   dst = (const int*)d_in[2];
    const float* W1  = (const float*)d_in[3];
    const float* al1 = (const float*)d_in[4];
    const float* ar1 = (const float*)d_in[5];
    const float* b1  = (const float*)d_in[6];
    const float* W2  = (const float*)d_in[7];
    const float* al2 = (const float*)d_in[8];
    const float* ar2 = (const float*)d_in[9];
    const float* b2  = (const float*)d_in[10];
    const float* W3  = (const float*)d_in[11];
    const float* al3 = (const float*)d_in[12];
    const float* ar3 = (const float*)d_in[13];
    const float* b3  = (const float*)d_in[14];
    float* out = (float*)d_out;

    const int GEMM_BLOCKS = (NN + 127) / 128;
    const int NODE_BLOCKS = (NN + 7) / 8;
    const int E4_BLOCKS = (EE / 4 + 255) / 256;

    // zero cnt via capturable async memset
    void* p_cnt = nullptr;
    cudaGetSymbolAddress(&p_cnt, d_cnt);
    cudaMemsetAsync(p_cnt, 0, NN * sizeof(int));

    // CSR build (reused by all 3 layers)
    count_kernel<<<E4_BLOCKS, 256>>>((const int4*)dst);
    csr_blocksum_kernel<<<SCAN_NB, SCAN_BS>>>();
    csr_scanb_kernel<<<1, SCAN_BS>>>();
    csr_emit_kernel<<<SCAN_NB, SCAN_BS>>>();
    scatter_kernel<<<E4_BLOCKS, 256>>>((const int4*)src, (const int4*)dst);

    // layer 1
    gemm_tc_kernel<false><<<GEMM_BLOCKS, 256>>>(h, W1, al1, ar1);
    agg_kernel<0><<<NODE_BLOCKS, 256>>>(b1, nullptr);

    // layer 2
    gemm_tc_kernel<true><<<GEMM_BLOCKS, 256>>>(nullptr, W2, al2, ar2);
    agg_kernel<0><<<NODE_BLOCKS, 256>>>(b2, nullptr);

    // layer 3
    gemm_tc_kernel<true><<<GEMM_BLOCKS, 256>>>(nullptr, W3, al3, ar3);
    agg_kernel<1><<<NODE_BLOCKS, 256>>>(b3, out);
}

// round 10
// speedup vs baseline: 1.0773x; 1.0128x over previous
#include <cuda_runtime.h>
#include <cuda_fp16.h>
#include <math.h>

#define NN 50000
#define EE 1600000
#define FDIM 128
#define NHEAD 4
#define SCAN_BS 256
#define SCAN_NB ((NN + SCAN_BS - 1) / SCAN_BS)   // 196

// ---------------- scratch (device globals, no allocation) ----------------
__device__ __half d_fth[NN * FDIM]; // transposed per-node features fp16: [n][d*4+h]
__device__ __half d_xh[NN * FDIM];  // inter-layer activations fp16: [n][h*32+d]
__device__ float d_el[NN * NHEAD];
__device__ float d_er[NN * NHEAD];
__device__ int   d_cnt[NN];
__device__ int   d_rowptr[NN + 1];
__device__ int   d_rowpos[NN];
__device__ int   d_esrc[EE];
__device__ int   d_bsum[SCAN_NB];
__device__ int   d_boff[SCAN_NB];
__device__ int   d_scan_ctr;        // zero-initialized; self-resetting each run

// ---------------- CSR build ----------------
// int4-vectorized: 1 LDG.128 covers 4 edges -> 4x per-warp MLP
__global__ void count_kernel(const int4* __restrict__ dst4) {
    int i = blockIdx.x * blockDim.x + threadIdx.x;
    if (i < EE / 4) {
        int4 d = dst4[i];
        atomicAdd(&d_cnt[d.x], 1);
        atomicAdd(&d_cnt[d.y], 1);
        atomicAdd(&d_cnt[d.z], 1);
        atomicAdd(&d_cnt[d.w], 1);
    }
}

// fused phase A+B: per-block sums; last arriving block scans the block sums.
__global__ __launch_bounds__(SCAN_BS) void csr_blocksum_scan_kernel() {
    __shared__ int sh[SCAN_BS];
    __shared__ bool s_last;
    int t = threadIdx.x;
    int i = blockIdx.x * SCAN_BS + t;
    int v = (i < NN) ? d_cnt[i] : 0;
    sh[t] = v;
    __syncthreads();
    for (int d = SCAN_BS / 2; d > 0; d >>= 1) {
        if (t < d) sh[t] += sh[t + d];
        __syncthreads();
    }
    if (t == 0) {
        d_bsum[blockIdx.x] = sh[0];
        __threadfence();
        int ticket = atomicAdd(&d_scan_ctr, 1);
        s_last = (ticket == SCAN_NB - 1);
    }
    __syncthreads();
    if (s_last) {
        // this block performs the exclusive scan of the 196 block sums
        int x = (t < SCAN_NB) ? d_bsum[t] : 0;
        int orig = x;
        sh[t] = x;
        __syncthreads();
        for (int d = 1; d < SCAN_BS; d <<= 1) {
            int y = sh[t];
            int add = (t >= d) ? sh[t - d] : 0;
            __syncthreads();
            sh[t] = y + add;
            __syncthreads();
        }
        if (t < SCAN_NB) d_boff[t] = sh[t] - orig;   // exclusive
        if (t == SCAN_NB - 1) d_rowptr[NN] = sh[t];
        if (t == 0) d_scan_ctr = 0;                   // self-reset for next replay
    }
}

// phase C: block-local exclusive scan + global offset -> rowptr/rowpos
__global__ __launch_bounds__(SCAN_BS) void csr_emit_kernel() {
    __shared__ int sh[SCAN_BS];
    int t = threadIdx.x;
    int i = blockIdx.x * SCAN_BS + t;
    int v = (i < NN) ? d_cnt[i] : 0;
    sh[t] = v;
    __syncthreads();
    for (int d = 1; d < SCAN_BS; d <<= 1) {
        int x = sh[t];
        int add = (t >= d) ? sh[t - d] : 0;
        __syncthreads();
        sh[t] = x + add;
        __syncthreads();
    }
    if (i < NN) {
        int off = d_boff[blockIdx.x] + sh[t] - v;   // exclusive prefix
        d_rowptr[i] = off;
        d_rowpos[i] = off;
    }
}

__global__ void scatter_kernel(const int4* __restrict__ src4, const int4* __restrict__ dst4) {
    int i = blockIdx.x * blockDim.x + threadIdx.x;
    if (i < EE / 4) {
        int4 s = src4[i];
        int4 d = dst4[i];
        int p0 = atomicAdd(&d_rowpos[d.x], 1);
        int p1 = atomicAdd(&d_rowpos[d.y], 1);
        int p2 = atomicAdd(&d_rowpos[d.z], 1);
        int p3 = atomicAdd(&d_rowpos[d.w], 1);
        d_esrc[p0] = s.x;
        d_esrc[p1] = s.y;
        d_esrc[p2] = s.z;
        d_esrc[p3] = s.w;
    }
}

// ---------------- tensor-core GEMM ----------------
__device__ __forceinline__ void mma16816(float* d,
                                         unsigned a0, unsigned a1, unsigned a2, unsigned a3,
                                         unsigned b0, unsigned b1) {
    asm volatile(
        "mma.sync.aligned.m16n8k16.row.col.f32.f16.f16.f32 "
        "{%0,%1,%2,%3}, {%4,%5,%6,%7}, {%8,%9}, {%0,%1,%2,%3};"
        : "+f"(d[0]), "+f"(d[1]), "+f"(d[2]), "+f"(d[3])
        : "r"(a0), "r"(a1), "r"(a2), "r"(a3), "r"(b0), "r"(b1));
}
__device__ __forceinline__ unsigned f2h2(float lo, float hi) {
    __half2 h = __floats2half2_rn(lo, hi);
    return *reinterpret_cast<unsigned*>(&h);
}

// ft = x @ W -> fp16 transposed [n][d*4+h], fused el/er (fp32), via HMMA m16n8k16.
// Block: 256 threads (8 warps), 128 rows/block, full N=128, K=128 (8 k-steps).
// __launch_bounds__(256, 2): cap regs at 128 so 2 CTAs fit per SM.
#define WSTRIDE 136
template <bool X_IS_HALF>
__global__ __launch_bounds__(256, 2) void gemm_tc_kernel(const float* __restrict__ xin,
                                                         const float* __restrict__ W,
                                                         const float* __restrict__ al,
                                                         const float* __restrict__ ar) {
    __shared__ __half Wt[128 * WSTRIDE];   // union: W^T fp16 [n][k], then per-warp staging
    __shared__ float sal[128], sar[128];
    int t = threadIdx.x;
    int w = t >> 5, l = t & 31;
    int g = l >> 2, tig = l & 3;
    int row0 = blockIdx.x * 128;

    // W fp32 [k][n] -> Wt fp16 [n][k] (coalesced global read)
#pragma unroll
    for (int i = 0; i < 64; i++) {
        int idx = t + 256 * i;
        int k = idx >> 7, n = idx & 127;
        Wt[n * WSTRIDE + k] = __float2half(W[idx]);
    }
    if (t < 128) sal[t] = al[t];
    else sar[t - 128] = ar[t - 128];
    __syncthreads();

    float acc[16][4];
#pragma unroll
    for (int nt = 0; nt < 16; nt++)
#pragma unroll
        for (int j = 0; j < 4; j++) acc[nt][j] = 0.f;

    int r1 = row0 + w * 16 + g;   // rows this thread's fragments cover
    int r2 = r1 + 8;
    bool ok1 = r1 < NN, ok2 = r2 < NN;

#pragma unroll
    for (int ks = 0; ks < 8; ks++) {
        int k0 = ks * 16 + 2 * tig;
        unsigned a0 = 0, a1 = 0, a2 = 0, a3 = 0;
        if (X_IS_HALF) {
            if (ok1) {
                a0 = *reinterpret_cast<const unsigned*>(&d_xh[r1 * 128 + k0]);
                a2 = *reinterpret_cast<const unsigned*>(&d_xh[r1 * 128 + k0 + 8]);
            }
            if (ok2) {
                a1 = *reinterpret_cast<const unsigned*>(&d_xh[r2 * 128 + k0]);
                a3 = *reinterpret_cast<const unsigned*>(&d_xh[r2 * 128 + k0 + 8]);
            }
        } else {
            if (ok1) {
                float2 f = *reinterpret_cast<const float2*>(&xin[r1 * 128 + k0]);
                a0 = f2h2(f.x, f.y);
                f = *reinterpret_cast<const float2*>(&xin[r1 * 128 + k0 + 8]);
                a2 = f2h2(f.x, f.y);
            }
            if (ok2) {
                float2 f = *reinterpret_cast<const float2*>(&xin[r2 * 128 + k0]);
                a1 = f2h2(f.x, f.y);
                f = *reinterpret_cast<const float2*>(&xin[r2 * 128 + k0 + 8]);
                a3 = f2h2(f.x, f.y);
            }
        }
#pragma unroll
        for (int nt = 0; nt < 16; nt++) {
            const __half* bp = &Wt[(nt * 8 + g) * WSTRIDE + k0];
            unsigned b0 = *reinterpret_cast<const unsigned*>(bp);
            unsigned b1 = *reinterpret_cast<const unsigned*>(bp + 8);
            mma16816(acc[nt], a0, a1, a2, a3, b0, b1);
        }
    }

    // fused el/er from fragments: col c = nt*8 + 2*tig (+1); head = nt>>2
    {
        float pll[4] = {0, 0, 0, 0}, plh[4] = {0, 0, 0, 0};
        float prl[4] = {0, 0, 0, 0}, prh[4] = {0, 0, 0, 0};
#pragma unroll
        for (int nt = 0; nt < 16; nt++) {
            int hh = nt >> 2;
            int c = nt * 8 + 2 * tig;
            float s0 = sal[c], s1 = sal[c + 1];
            float u0 = sar[c], u1 = sar[c + 1];
            pll[hh] += acc[nt][0] * s0 + acc[nt][1] * s1;
            plh[hh] += acc[nt][2] * s0 + acc[nt][3] * s1;
            prl[hh] += acc[nt][0] * u0 + acc[nt][1] * u1;
            prh[hh] += acc[nt][2] * u0 + acc[nt][3] * u1;
        }
#pragma unroll
        for (int o = 1; o <= 2; o <<= 1) {
#pragma unroll
            for (int hh = 0; hh < 4; hh++) {
                pll[hh] += __shfl_xor_sync(0xffffffffu, pll[hh], o);
                plh[hh] += __shfl_xor_sync(0xffffffffu, plh[hh], o);
                prl[hh] += __shfl_xor_sync(0xffffffffu, prl[hh], o);
                prh[hh] += __shfl_xor_sync(0xffffffffu, prh[hh], o);
            }
        }
        if (tig == 0) {
            if (ok1) {
                *reinterpret_cast<float4*>(&d_el[r1 * 4]) = make_float4(pll[0], pll[1], pll[2], pll[3]);
                *reinterpret_cast<float4*>(&d_er[r1 * 4]) = make_float4(prl[0], prl[1], prl[2], prl[3]);
            }
            if (ok2) {
                *reinterpret_cast<float4*>(&d_el[r2 * 4]) = make_float4(plh[0], plh[1], plh[2], plh[3]);
                *reinterpret_cast<float4*>(&d_er[r2 * 4]) = make_float4(prh[0], prh[1], prh[2], prh[3]);
            }
        }
    }

    // stage D (fp16) per warp, then write ft transposed [r][d*4+h]
    __syncthreads();   // all warps done reading Wt
    __half* stg = &Wt[w * 16 * WSTRIDE];
#pragma unroll
    for (int nt = 0; nt < 16; nt++) {
        int c = nt * 8 + 2 * tig;
        *reinterpret_cast<unsigned*>(&stg[g * WSTRIDE + c]) = f2h2(acc[nt][0], acc[nt][1]);
        *reinterpret_cast<unsigned*>(&stg[(g + 8) * WSTRIDE + c]) = f2h2(acc[nt][2], acc[nt][3]);
    }
    __syncwarp();
#pragma unroll
    for (int r = 0; r < 16; r++) {
        int rr = row0 + w * 16 + r;
        if (rr < NN) {
            __half v0 = stg[r * WSTRIDE + l];
            __half v1 = stg[r * WSTRIDE + 32 + l];
            __half v2 = stg[r * WSTRIDE + 64 + l];
            __half v3 = stg[r * WSTRIDE + 96 + l];
            __half2 p01 = __halves2half2(v0, v1);
            __half2 p23 = __halves2half2(v2, v3);
            uint2 o;
            o.x = *reinterpret_cast<unsigned*>(&p01);
            o.y = *reinterpret_cast<unsigned*>(&p23);
            *reinterpret_cast<uint2*>(&d_fth[rr * 128 + l * 4]) = o;
        }
    }
}

// ---------------- per-dst-node softmax + aggregation, single pass (no max) ----------------
// MODE 0: write ELU(result) as fp16 into d_xh ([n][h*32+d]). MODE 1: write mean over heads into out.
template <int MODE>
__global__ __launch_bounds__(256) void agg_kernel(const float* __restrict__ bias,
                                                  float* __restrict__ out) {
    __shared__ float4 sw[8][32];
    __shared__ int ss[8][32];
    int warp = threadIdx.x >> 5, lane = threadIdx.x & 31;
    int n = blockIdx.x * 8 + warp;
    if (n >= NN) return;
    int start = d_rowptr[n], end = d_rowptr[n + 1];
    float4 ern = *reinterpret_cast<const float4*>(&d_er[n * 4]);

    float acc0 = 0.f, acc1 = 0.f, acc2 = 0.f, acc3 = 0.f;
    float z0 = 0.f, z1 = 0.f, z2 = 0.f, z3 = 0.f;

    for (int c = start; c < end; c += 32) {
        int idx = c + lane;
        int s = 0;
        float4 w = make_float4(0.f, 0.f, 0.f, 0.f);
        if (idx < end) {
            s = d_esrc[idx];
            float4 e4 = *reinterpret_cast<const float4*>(&d_el[s * 4]);
            float e;
            e = e4.x + ern.x; e = e > 0.f ? e : 0.2f * e; w.x = __expf(e);
            e = e4.y + ern.y; e = e > 0.f ? e : 0.2f * e; w.y = __expf(e);
            e = e4.z + ern.z; e = e > 0.f ? e : 0.2f * e; w.z = __expf(e);
            e = e4.w + ern.w; e = e > 0.f ? e : 0.2f * e; w.w = __expf(e);
            z0 += w.x; z1 += w.y; z2 += w.z; z3 += w.w;
        }
        ss[warp][lane] = s;
        sw[warp][lane] = w;
        __syncwarp();
        int cnt = end - c; if (cnt > 32) cnt = 32;
        int j = 0;
        // 4-wide batches: 4 independent LDG.64 in flight before the FMAs
        for (; j + 4 <= cnt; j += 4) {
            int sa = ss[warp][j], sb = ss[warp][j + 1];
            int sc = ss[warp][j + 2], sd = ss[warp][j + 3];
            float4 wa = sw[warp][j], wb = sw[warp][j + 1];
            float4 wc = sw[warp][j + 2], wd = sw[warp][j + 3];
            uint2 fa = *reinterpret_cast<const uint2*>(&d_fth[sa * 128 + lane * 4]);
            uint2 fb = *reinterpret_cast<const uint2*>(&d_fth[sb * 128 + lane * 4]);
            uint2 fc = *reinterpret_cast<const uint2*>(&d_fth[sc * 128 + lane * 4]);
            uint2 fd = *reinterpret_cast<const uint2*>(&d_fth[sd * 128 + lane * 4]);
            float2 a01 = __half22float2(*reinterpret_cast<__half2*>(&fa.x));
            float2 a23 = __half22float2(*reinterpret_cast<__half2*>(&fa.y));
            float2 b01 = __half22float2(*reinterpret_cast<__half2*>(&fb.x));
            float2 b23 = __half22float2(*reinterpret_cast<__half2*>(&fb.y));
            float2 c01 = __half22float2(*reinterpret_cast<__half2*>(&fc.x));
            float2 c23 = __half22float2(*reinterpret_cast<__half2*>(&fc.y));
            float2 d01 = __half22float2(*reinterpret_cast<__half2*>(&fd.x));
            float2 d23 = __half22float2(*reinterpret_cast<__half2*>(&fd.y));
            acc0 += wa.x * a01.x; acc1 += wa.y * a01.y; acc2 += wa.z * a23.x; acc3 += wa.w * a23.y;
            acc0 += wb.x * b01.x; acc1 += wb.y * b01.y; acc2 += wb.z * b23.x; acc3 += wb.w * b23.y;
            acc0 += wc.x * c01.x; acc1 += wc.y * c01.y; acc2 += wc.z * c23.x; acc3 += wc.w * c23.y;
            acc0 += wd.x * d01.x; acc1 += wd.y * d01.y; acc2 += wd.z * d23.x; acc3 += wd.w * d23.y;
        }
        for (; j < cnt; j++) {
            int s2 = ss[warp][j];
            float4 wv = sw[warp][j];
            uint2 f = *reinterpret_cast<const uint2*>(&d_fth[s2 * 128 + lane * 4]);
            float2 f01 = __half22float2(*reinterpret_cast<__half2*>(&f.x));
            float2 f23 = __half22float2(*reinterpret_cast<__half2*>(&f.y));
            acc0 += wv.x * f01.x; acc1 += wv.y * f01.y;
            acc2 += wv.z * f23.x; acc3 += wv.w * f23.y;
        }
        __syncwarp();
    }
#pragma unroll
    for (int o = 16; o > 0; o >>= 1) {
        z0 += __shfl_xor_sync(0xffffffffu, z0, o);
        z1 += __shfl_xor_sync(0xffffffffu, z1, o);
        z2 += __shfl_xor_sync(0xffffffffu, z2, o);
        z3 += __shfl_xor_sync(0xffffffffu, z3, o);
    }

    float v0 = (z0 > 0.f ? acc0 / z0 : 0.f) + bias[0 * 32 + lane];
    float v1 = (z1 > 0.f ? acc1 / z1 : 0.f) + bias[1 * 32 + lane];
    float v2 = (z2 > 0.f ? acc2 / z2 : 0.f) + bias[2 * 32 + lane];
    float v3 = (z3 > 0.f ? acc3 / z3 : 0.f) + bias[3 * 32 + lane];

    if (MODE == 0) {
        v0 = v0 > 0.f ? v0 : __expf(v0) - 1.f;
        v1 = v1 > 0.f ? v1 : __expf(v1) - 1.f;
        v2 = v2 > 0.f ? v2 : __expf(v2) - 1.f;
        v3 = v3 > 0.f ? v3 : __expf(v3) - 1.f;
        d_xh[n * 128 + 0 * 32 + lane] = __float2half(v0);
        d_xh[n * 128 + 1 * 32 + lane] = __float2half(v1);
        d_xh[n * 128 + 2 * 32 + lane] = __float2half(v2);
        d_xh[n * 128 + 3 * 32 + lane] = __float2half(v3);
    } else {
        out[n * 32 + lane] = (v0 + v1 + v2 + v3) * 0.25f;
    }
}

// ---------------- launch ----------------
extern "C" void kernel_launch(void* const* d_in, const int* in_sizes, int n_in,
                              void* d_out, int out_size) {
    const float* h   = (const float*)d_in[0];
    const int*   src = (const int*)d_in[1];
    const int*   dst = (const int*)d_in[2];
    const float* W1  = (const float*)d_in[3];
    const float* al1 = (const float*)d_in[4];
    const float* ar1 = (const float*)d_in[5];
    const float* b1  = (const float*)d_in[6];
    const float* W2  = (const float*)d_in[7];
    const float* al2 = (const float*)d_in[8];
    const float* ar2 = (const float*)d_in[9];
    const float* b2  = (const float*)d_in[10];
    const float* W3  = (const float*)d_in[11];
    const float* al3 = (const float*)d_in[12];
    const float* ar3 = (const float*)d_in[13];
    const float* b3  = (const float*)d_in[14];
    float* out = (float*)d_out;

    const int GEMM_BLOCKS = (NN + 127) / 128;
    const int NODE_BLOCKS = (NN + 7) / 8;
    const int E4_BLOCKS = (EE / 4 + 255) / 256;

    // lazily-created side stream + events (created on first/correctness call,
    // reused for every call; no device-memory allocation involved)
    static cudaStream_t s2 = nullptr;
    static cudaEvent_t evFork = nullptr, evJoin = nullptr;
    if (s2 == nullptr) {
        cudaStreamCreateWithFlags(&s2, cudaStreamNonBlocking);
        cudaEventCreateWithFlags(&evFork, cudaEventDisableTiming);
        cudaEventCreateWithFlags(&evJoin, cudaEventDisableTiming);
    }

    // fork: layer-1 GEMM (independent of CSR build) runs on s2
    cudaEventRecord(evFork, 0);
    cudaStreamWaitEvent(s2, evFork, 0);
    gemm_tc_kernel<false><<<GEMM_BLOCKS, 256, 0, s2>>>(h, W1, al1, ar1);
    cudaEventRecord(evJoin, s2);

    // main stream: CSR build (reused by all 3 layers)
    void* p_cnt = nullptr;
    cudaGetSymbolAddress(&p_cnt, d_cnt);
    cudaMemsetAsync(p_cnt, 0, NN * sizeof(int));
    count_kernel<<<E4_BLOCKS, 256>>>((const int4*)dst);
    csr_blocksum_scan_kernel<<<SCAN_NB, SCAN_BS>>>();
    csr_emit_kernel<<<SCAN_NB, SCAN_BS>>>();
    scatter_kernel<<<E4_BLOCKS, 256>>>((const int4*)src, (const int4*)dst);

    // join: agg1 needs both CSR and GEMM1 results
    cudaStreamWaitEvent(0, evJoin, 0);
    agg_kernel<0><<<NODE_BLOCKS, 256>>>(b1, nullptr);

    // layer 2
    gemm_tc_kernel<true><<<GEMM_BLOCKS, 256>>>(nullptr, W2, al2, ar2);
    agg_kernel<0><<<NODE_BLOCKS, 256>>>(b2, nullptr);

    // layer 3
    gemm_tc_kernel<true><<<GEMM_BLOCKS, 256>>>(nullptr, W3, al3, ar3);
    agg_kernel<1><<<NODE_BLOCKS, 256>>>(b3, out);
}

// round 11
// speedup vs baseline: 1.0853x; 1.0074x over previous
#include <cuda_runtime.h>
#include <cuda_fp16.h>
#include <math.h>

#define NN 50000
#define EE 1600000
#define FDIM 128
#define NHEAD 4
#define SCAN_BS 256
#define SCAN_NB ((NN + SCAN_BS - 1) / SCAN_BS)   // 196

// ---------------- scratch (device globals, no allocation) ----------------
__device__ __half d_fth[NN * FDIM]; // transposed per-node features fp16: [n][d*4+h]
__device__ __half d_xh[NN * FDIM];  // inter-layer activations fp16: [n][h*32+d]
__device__ float d_el[NN * NHEAD];
__device__ float d_er[NN * NHEAD];
__device__ int   d_cnt[NN];         // zero-init; self-cleaned each run
__device__ int   d_rowptr[NN + 1];
__device__ int   d_rowpos[NN];
__device__ int   d_esrc[EE];
__device__ int   d_bsum[SCAN_NB];
__device__ int   d_boff[SCAN_NB];
__device__ int   d_scan_ctr;        // ticket: which block arrived last
__device__ int   d_done_ctr;        // ticket: which block finished last (does reset)
__device__ int   d_scan_flag;       // boff published flag

// ---------------- CSR build ----------------
// int4-vectorized: 1 LDG.128 covers 4 edges -> 4x per-warp MLP
__global__ void count_kernel(const int4* __restrict__ dst4) {
    int i = blockIdx.x * blockDim.x + threadIdx.x;
    if (i < EE / 4) {
        int4 d = dst4[i];
        atomicAdd(&d_cnt[d.x], 1);
        atomicAdd(&d_cnt[d.y], 1);
        atomicAdd(&d_cnt[d.z], 1);
        atomicAdd(&d_cnt[d.w], 1);
    }
}

// Fused scan+emit, grid-resident (196 blocks all fit in wave 1):
//  - each block scans its 256 cnt values (read once) and zeroes cnt (self-clean)
//  - last-arriving block scans the 196 block sums, publishes d_boff + flag
//  - all blocks spin on the flag, then emit rowptr/rowpos
//  - last-finishing block resets tickets/flag for the next graph replay
__global__ __launch_bounds__(SCAN_BS) void csr_scan_emit_kernel() {
    __shared__ int sh[SCAN_BS];
    __shared__ bool s_last;
    __shared__ int s_boff;
    int b = blockIdx.x, t = threadIdx.x;
    int i = b * SCAN_BS + t;
    int v = (i < NN) ? d_cnt[i] : 0;
    if (i < NN) d_cnt[i] = 0;        // self-clean for the next replay

    // Hillis-Steele inclusive scan of the block's 256 values
    sh[t] = v;
    __syncthreads();
    for (int d = 1; d < SCAN_BS; d <<= 1) {
        int x = sh[t];
        int add = (t >= d) ? sh[t - d] : 0;
        __syncthreads();
        sh[t] = x + add;
        __syncthreads();
    }
    int incl = sh[t];
    int total = sh[SCAN_BS - 1];

    volatile int* vflag = &d_scan_flag;
    if (t == 0) {
        d_bsum[b] = total;
        __threadfence();
        int ticket = atomicAdd(&d_scan_ctr, 1);
        s_last = (ticket == SCAN_NB - 1);
    }
    __syncthreads();

    if (s_last) {
        // this block scans the 196 block sums (needs sh[] again)
        __syncthreads();
        int x = (t < SCAN_NB) ? d_bsum[t] : 0;
        int orig = x;
        sh[t] = x;
        __syncthreads();
        for (int d = 1; d < SCAN_BS; d <<= 1) {
            int y = sh[t];
            int add = (t >= d) ? sh[t - d] : 0;
            __syncthreads();
            sh[t] = y + add;
            __syncthreads();
        }
        if (t < SCAN_NB) d_boff[t] = sh[t] - orig;   // exclusive
        if (t == SCAN_NB - 1) d_rowptr[NN] = sh[t];
        __threadfence();
        if (t == 0) *vflag = 1;
    }

    // wait for boff publication, then emit
    if (t == 0) {
        while (*vflag == 0) {}
        __threadfence();
        s_boff = d_boff[b];
    }
    __syncthreads();
    if (i < NN) {
        int off = s_boff + incl - v;    // exclusive prefix
        d_rowptr[i] = off;
        d_rowpos[i] = off;
    }
    __syncthreads();
    if (t == 0) {
        int ticket2 = atomicAdd(&d_done_ctr, 1);
        if (ticket2 == SCAN_NB - 1) {   // all blocks done: reset state for next replay
            d_scan_flag = 0;
            d_scan_ctr = 0;
            d_done_ctr = 0;
        }
    }
}

__global__ void scatter_kernel(const int4* __restrict__ src4, const int4* __restrict__ dst4) {
    int i = blockIdx.x * blockDim.x + threadIdx.x;
    if (i < EE / 4) {
        int4 s = src4[i];
        int4 d = dst4[i];
        int p0 = atomicAdd(&d_rowpos[d.x], 1);
        int p1 = atomicAdd(&d_rowpos[d.y], 1);
        int p2 = atomicAdd(&d_rowpos[d.z], 1);
        int p3 = atomicAdd(&d_rowpos[d.w], 1);
        d_esrc[p0] = s.x;
        d_esrc[p1] = s.y;
        d_esrc[p2] = s.z;
        d_esrc[p3] = s.w;
    }
}

// ---------------- tensor-core GEMM ----------------
__device__ __forceinline__ void mma16816(float* d,
                                         unsigned a0, unsigned a1, unsigned a2, unsigned a3,
                                         unsigned b0, unsigned b1) {
    asm volatile(
        "mma.sync.aligned.m16n8k16.row.col.f32.f16.f16.f32 "
        "{%0,%1,%2,%3}, {%4,%5,%6,%7}, {%8,%9}, {%0,%1,%2,%3};"
        : "+f"(d[0]), "+f"(d[1]), "+f"(d[2]), "+f"(d[3])
        : "r"(a0), "r"(a1), "r"(a2), "r"(a3), "r"(b0), "r"(b1));
}
__device__ __forceinline__ unsigned f2h2(float lo, float hi) {
    __half2 h = __floats2half2_rn(lo, hi);
    return *reinterpret_cast<unsigned*>(&h);
}

// ft = x @ W -> fp16 transposed [n][d*4+h], fused el/er (fp32), via HMMA m16n8k16.
// Block: 256 threads (8 warps), 128 rows/block, full N=128, K=128 (8 k-steps).
// __launch_bounds__(256, 2): cap regs at 128 so 2 CTAs fit per SM.
#define WSTRIDE 136
template <bool X_IS_HALF>
__global__ __launch_bounds__(256, 2) void gemm_tc_kernel(const float* __restrict__ xin,
                                                         const float* __restrict__ W,
                                                         const float* __restrict__ al,
                                                         const float* __restrict__ ar) {
    __shared__ __half Wt[128 * WSTRIDE];   // union: W^T fp16 [n][k], then per-warp staging
    __shared__ float sal[128], sar[128];
    int t = threadIdx.x;
    int w = t >> 5, l = t & 31;
    int g = l >> 2, tig = l & 3;
    int row0 = blockIdx.x * 128;

    // W fp32 [k][n] -> Wt fp16 [n][k] (coalesced global read)
#pragma unroll
    for (int i = 0; i < 64; i++) {
        int idx = t + 256 * i;
        int k = idx >> 7, n = idx & 127;
        Wt[n * WSTRIDE + k] = __float2half(W[idx]);
    }
    if (t < 128) sal[t] = al[t];
    else sar[t - 128] = ar[t - 128];
    __syncthreads();

    float acc[16][4];
#pragma unroll
    for (int nt = 0; nt < 16; nt++)
#pragma unroll
        for (int j = 0; j < 4; j++) acc[nt][j] = 0.f;

    int r1 = row0 + w * 16 + g;   // rows this thread's fragments cover
    int r2 = r1 + 8;
    bool ok1 = r1 < NN, ok2 = r2 < NN;

#pragma unroll
    for (int ks = 0; ks < 8; ks++) {
        int k0 = ks * 16 + 2 * tig;
        unsigned a0 = 0, a1 = 0, a2 = 0, a3 = 0;
        if (X_IS_HALF) {
            if (ok1) {
                a0 = *reinterpret_cast<const unsigned*>(&d_xh[r1 * 128 + k0]);
                a2 = *reinterpret_cast<const unsigned*>(&d_xh[r1 * 128 + k0 + 8]);
            }
            if (ok2) {
                a1 = *reinterpret_cast<const unsigned*>(&d_xh[r2 * 128 + k0]);
                a3 = *reinterpret_cast<const unsigned*>(&d_xh[r2 * 128 + k0 + 8]);
            }
        } else {
            if (ok1) {
                float2 f = *reinterpret_cast<const float2*>(&xin[r1 * 128 + k0]);
                a0 = f2h2(f.x, f.y);
                f = *reinterpret_cast<const float2*>(&xin[r1 * 128 + k0 + 8]);
                a2 = f2h2(f.x, f.y);
            }
            if (ok2) {
                float2 f = *reinterpret_cast<const float2*>(&xin[r2 * 128 + k0]);
                a1 = f2h2(f.x, f.y);
                f = *reinterpret_cast<const float2*>(&xin[r2 * 128 + k0 + 8]);
                a3 = f2h2(f.x, f.y);
            }
        }
#pragma unroll
        for (int nt = 0; nt < 16; nt++) {
            const __half* bp = &Wt[(nt * 8 + g) * WSTRIDE + k0];
            unsigned b0 = *reinterpret_cast<const unsigned*>(bp);
            unsigned b1 = *reinterpret_cast<const unsigned*>(bp + 8);
            mma16816(acc[nt], a0, a1, a2, a3, b0, b1);
        }
    }

    // fused el/er from fragments: col c = nt*8 + 2*tig (+1); head = nt>>2
    {
        float pll[4] = {0, 0, 0, 0}, plh[4] = {0, 0, 0, 0};
        float prl[4] = {0, 0, 0, 0}, prh[4] = {0, 0, 0, 0};
#pragma unroll
        for (int nt = 0; nt < 16; nt++) {
            int hh = nt >> 2;
            int c = nt * 8 + 2 * tig;
            float s0 = sal[c], s1 = sal[c + 1];
            float u0 = sar[c], u1 = sar[c + 1];
            pll[hh] += acc[nt][0] * s0 + acc[nt][1] * s1;
            plh[hh] += acc[nt][2] * s0 + acc[nt][3] * s1;
            prl[hh] += acc[nt][0] * u0 + acc[nt][1] * u1;
            prh[hh] += acc[nt][2] * u0 + acc[nt][3] * u1;
        }
#pragma unroll
        for (int o = 1; o <= 2; o <<= 1) {
#pragma unroll
            for (int hh = 0; hh < 4; hh++) {
                pll[hh] += __shfl_xor_sync(0xffffffffu, pll[hh], o);
                plh[hh] += __shfl_xor_sync(0xffffffffu, plh[hh], o);
                prl[hh] += __shfl_xor_sync(0xffffffffu, prl[hh], o);
                prh[hh] += __shfl_xor_sync(0xffffffffu, prh[hh], o);
            }
        }
        if (tig == 0) {
            if (ok1) {
                *reinterpret_cast<float4*>(&d_el[r1 * 4]) = make_float4(pll[0], pll[1], pll[2], pll[3]);
                *reinterpret_cast<float4*>(&d_er[r1 * 4]) = make_float4(prl[0], prl[1], prl[2], prl[3]);
            }
            if (ok2) {
                *reinterpret_cast<float4*>(&d_el[r2 * 4]) = make_float4(plh[0], plh[1], plh[2], plh[3]);
                *reinterpret_cast<float4*>(&d_er[r2 * 4]) = make_float4(prh[0], prh[1], prh[2], prh[3]);
            }
        }
    }

    // stage D (fp16) per warp, then write ft transposed [r][d*4+h]
    __syncthreads();   // all warps done reading Wt
    __half* stg = &Wt[w * 16 * WSTRIDE];
#pragma unroll
    for (int nt = 0; nt < 16; nt++) {
        int c = nt * 8 + 2 * tig;
        *reinterpret_cast<unsigned*>(&stg[g * WSTRIDE + c]) = f2h2(acc[nt][0], acc[nt][1]);
        *reinterpret_cast<unsigned*>(&stg[(g + 8) * WSTRIDE + c]) = f2h2(acc[nt][2], acc[nt][3]);
    }
    __syncwarp();
#pragma unroll
    for (int r = 0; r < 16; r++) {
        int rr = row0 + w * 16 + r;
        if (rr < NN) {
            __half v0 = stg[r * WSTRIDE + l];
            __half v1 = stg[r * WSTRIDE + 32 + l];
            __half v2 = stg[r * WSTRIDE + 64 + l];
            __half v3 = stg[r * WSTRIDE + 96 + l];
            __half2 p01 = __halves2half2(v0, v1);
            __half2 p23 = __halves2half2(v2, v3);
            uint2 o;
            o.x = *reinterpret_cast<unsigned*>(&p01);
            o.y = *reinterpret_cast<unsigned*>(&p23);
            *reinterpret_cast<uint2*>(&d_fth[rr * 128 + l * 4]) = o;
        }
    }
}

// ---------------- per-dst-node softmax + aggregation, single pass (no max) ----------------
// MODE 0: write ELU(result) as fp16 into d_xh ([n][h*32+d]). MODE 1: write mean over heads into out.
template <int MODE>
__global__ __launch_bounds__(256) void agg_kernel(const float* __restrict__ bias,
                                                  float* __restrict__ out) {
    __shared__ float4 sw[8][32];
    __shared__ int ss[8][32];
    int warp = threadIdx.x >> 5, lane = threadIdx.x & 31;
    int n = blockIdx.x * 8 + warp;
    if (n >= NN) return;
    int start = d_rowptr[n], end = d_rowptr[n + 1];
    float4 ern = *reinterpret_cast<const float4*>(&d_er[n * 4]);

    float acc0 = 0.f, acc1 = 0.f, acc2 = 0.f, acc3 = 0.f;
    float z0 = 0.f, z1 = 0.f, z2 = 0.f, z3 = 0.f;

    for (int c = start; c < end; c += 32) {
        int idx = c + lane;
        int s = 0;
        float4 w = make_float4(0.f, 0.f, 0.f, 0.f);
        if (idx < end) {
            s = d_esrc[idx];
            float4 e4 = *reinterpret_cast<const float4*>(&d_el[s * 4]);
            float e;
            e = e4.x + ern.x; e = e > 0.f ? e : 0.2f * e; w.x = __expf(e);
            e = e4.y + ern.y; e = e > 0.f ? e : 0.2f * e; w.y = __expf(e);
            e = e4.z + ern.z; e = e > 0.f ? e : 0.2f * e; w.z = __expf(e);
            e = e4.w + ern.w; e = e > 0.f ? e : 0.2f * e; w.w = __expf(e);
            z0 += w.x; z1 += w.y; z2 += w.z; z3 += w.w;
        }
        ss[warp][lane] = s;
        sw[warp][lane] = w;
        __syncwarp();
        int cnt = end - c; if (cnt > 32) cnt = 32;
        int j = 0;
        // 4-wide batches: 4 independent LDG.64 in flight before the FMAs
        for (; j + 4 <= cnt; j += 4) {
            int sa = ss[warp][j], sb = ss[warp][j + 1];
            int sc = ss[warp][j + 2], sd = ss[warp][j + 3];
            float4 wa = sw[warp][j], wb = sw[warp][j + 1];
            float4 wc = sw[warp][j + 2], wd = sw[warp][j + 3];
            uint2 fa = *reinterpret_cast<const uint2*>(&d_fth[sa * 128 + lane * 4]);
            uint2 fb = *reinterpret_cast<const uint2*>(&d_fth[sb * 128 + lane * 4]);
            uint2 fc = *reinterpret_cast<const uint2*>(&d_fth[sc * 128 + lane * 4]);
            uint2 fd = *reinterpret_cast<const uint2*>(&d_fth[sd * 128 + lane * 4]);
            float2 a01 = __half22float2(*reinterpret_cast<__half2*>(&fa.x));
            float2 a23 = __half22float2(*reinterpret_cast<__half2*>(&fa.y));
            float2 b01 = __half22float2(*reinterpret_cast<__half2*>(&fb.x));
            float2 b23 = __half22float2(*reinterpret_cast<__half2*>(&fb.y));
            float2 c01 = __half22float2(*reinterpret_cast<__half2*>(&fc.x));
            float2 c23 = __half22float2(*reinterpret_cast<__half2*>(&fc.y));
            float2 d01 = __half22float2(*reinterpret_cast<__half2*>(&fd.x));
            float2 d23 = __half22float2(*reinterpret_cast<__half2*>(&fd.y));
            acc0 += wa.x * a01.x; acc1 += wa.y * a01.y; acc2 += wa.z * a23.x; acc3 += wa.w * a23.y;
            acc0 += wb.x * b01.x; acc1 += wb.y * b01.y; acc2 += wb.z * b23.x; acc3 += wb.w * b23.y;
            acc0 += wc.x * c01.x; acc1 += wc.y * c01.y; acc2 += wc.z * c23.x; acc3 += wc.w * c23.y;
            acc0 += wd.x * d01.x; acc1 += wd.y * d01.y; acc2 += wd.z * d23.x; acc3 += wd.w * d23.y;
        }
        for (; j < cnt; j++) {
            int s2 = ss[warp][j];
            float4 wv = sw[warp][j];
            uint2 f = *reinterpret_cast<const uint2*>(&d_fth[s2 * 128 + lane * 4]);
            float2 f01 = __half22float2(*reinterpret_cast<__half2*>(&f.x));
            float2 f23 = __half22float2(*reinterpret_cast<__half2*>(&f.y));
            acc0 += wv.x * f01.x; acc1 += wv.y * f01.y;
            acc2 += wv.z * f23.x; acc3 += wv.w * f23.y;
        }
        __syncwarp();
    }
#pragma unroll
    for (int o = 16; o > 0; o >>= 1) {
        z0 += __shfl_xor_sync(0xffffffffu, z0, o);
        z1 += __shfl_xor_sync(0xffffffffu, z1, o);
        z2 += __shfl_xor_sync(0xffffffffu, z2, o);
        z3 += __shfl_xor_sync(0xffffffffu, z3, o);
    }

    float v0 = (z0 > 0.f ? acc0 / z0 : 0.f) + bias[0 * 32 + lane];
    float v1 = (z1 > 0.f ? acc1 / z1 : 0.f) + bias[1 * 32 + lane];
    float v2 = (z2 > 0.f ? acc2 / z2 : 0.f) + bias[2 * 32 + lane];
    float v3 = (z3 > 0.f ? acc3 / z3 : 0.f) + bias[3 * 32 + lane];

    if (MODE == 0) {
        v0 = v0 > 0.f ? v0 : __expf(v0) - 1.f;
        v1 = v1 > 0.f ? v1 : __expf(v1) - 1.f;
        v2 = v2 > 0.f ? v2 : __expf(v2) - 1.f;
        v3 = v3 > 0.f ? v3 : __expf(v3) - 1.f;
        d_xh[n * 128 + 0 * 32 + lane] = __float2half(v0);
        d_xh[n * 128 + 1 * 32 + lane] = __float2half(v1);
        d_xh[n * 128 + 2 * 32 + lane] = __float2half(v2);
        d_xh[n * 128 + 3 * 32 + lane] = __float2half(v3);
    } else {
        out[n * 32 + lane] = (v0 + v1 + v2 + v3) * 0.25f;
    }
}

// ---------------- launch ----------------
extern "C" void kernel_launch(void* const* d_in, const int* in_sizes, int n_in,
                              void* d_out, int out_size) {
    const float* h   = (const float*)d_in[0];
    const int*   src = (const int*)d_in[1];
    const int*   dst = (const int*)d_in[2];
    const float* W1  = (const float*)d_in[3];
    const float* al1 = (const float*)d_in[4];
    const float* ar1 = (const float*)d_in[5];
    const float* b1  = (const float*)d_in[6];
    const float* W2  = (const float*)d_in[7];
    const float* al2 = (const float*)d_in[8];
    const float* ar2 = (const float*)d_in[9];
    const float* b2  = (const float*)d_in[10];
    const float* W3  = (const float*)d_in[11];
    const float* al3 = (const float*)d_in[12];
    const float* ar3 = (const float*)d_in[13];
    const float* b3  = (const float*)d_in[14];
    float* out = (float*)d_out;

    const int GEMM_BLOCKS = (NN + 127) / 128;
    const int NODE_BLOCKS = (NN + 7) / 8;
    const int E4_BLOCKS = (EE / 4 + 255) / 256;

    // lazily-created side stream + events (created on first/correctness call,
    // reused for every call; no device-memory allocation involved)
    static cudaStream_t s2 = nullptr;
    static cudaEvent_t evFork = nullptr, evJoin = nullptr;
    if (s2 == nullptr) {
        cudaStreamCreateWithFlags(&s2, cudaStreamNonBlocking);
        cudaEventCreateWithFlags(&evFork, cudaEventDisableTiming);
        cudaEventCreateWithFlags(&evJoin, cudaEventDisableTiming);
    }

    // fork: layer-1 GEMM (independent of CSR build) runs on s2
    cudaEventRecord(evFork, 0);
    cudaStreamWaitEvent(s2, evFork, 0);
    gemm_tc_kernel<false><<<GEMM_BLOCKS, 256, 0, s2>>>(h, W1, al1, ar1);
    cudaEventRecord(evJoin, s2);

    // main stream: CSR build (reused by all 3 layers)
    // d_cnt is zero at entry (static init on first run; self-cleaned by
    // csr_scan_emit_kernel on every run) -> no memset launch needed.
    count_kernel<<<E4_BLOCKS, 256>>>((const int4*)dst);
    csr_scan_emit_kernel<<<SCAN_NB, SCAN_BS>>>();
    scatter_kernel<<<E4_BLOCKS, 256>>>((const int4*)src, (const int4*)dst);

    // join: agg1 needs both CSR and GEMM1 results
    cudaStreamWaitEvent(0, evJoin, 0);
    agg_kernel<0><<<NODE_BLOCKS, 256>>>(b1, nullptr);

    // layer 2
    gemm_tc_kernel<true><<<GEMM_BLOCKS, 256>>>(nullptr, W2, al2, ar2);
    agg_kernel<0><<<NODE_BLOCKS, 256>>>(b2, nullptr);

    // layer 3
    gemm_tc_kernel<true><<<GEMM_BLOCKS, 256>>>(nullptr, W3, al3, ar3);
    agg_kernel<1><<<NODE_BLOCKS, 256>>>(b3, out);
}

// round 12
// speedup vs baseline: 1.0934x; 1.0075x over previous
#include <cuda_runtime.h>
#include <cuda_fp16.h>
#include <math.h>

#define NN 50000
#define EE 1600000
#define FDIM 128
#define NHEAD 4
#define SCAN_BS 256
#define SCAN_NB ((NN + SCAN_BS - 1) / SCAN_BS)   // 196

// ---------------- scratch (device globals, no allocation) ----------------
__device__ __half d_fth[NN * FDIM]; // transposed per-node features fp16: [n][d*4+h]
__device__ __half d_xh[NN * FDIM];  // inter-layer activations fp16: [n][h*32+d]
__device__ float d_el[NN * NHEAD];
__device__ float d_er[NN * NHEAD];
__device__ int   d_cnt[NN];         // zero-init; self-cleaned each run
__device__ int   d_rowptr[NN + 1];
__device__ int   d_esrc[EE];
__device__ int   d_eoff[EE];        // per-edge ticket (local offset within dst's segment)
__device__ int   d_bsum[SCAN_NB];
__device__ int   d_boff[SCAN_NB];
__device__ int   d_scan_ctr;        // ticket: which block arrived last
__device__ int   d_done_ctr;        // ticket: which block finished last (does reset)
__device__ int   d_scan_flag;       // boff published flag

// ---------------- CSR build ----------------
// Count + ticket capture: the atomicAdd return value IS the edge's local
// offset within its destination segment; store it so scatter needs no atomics.
__global__ void count_kernel(const int4* __restrict__ dst4) {
    int i = blockIdx.x * blockDim.x + threadIdx.x;
    if (i < EE / 4) {
        int4 d = dst4[i];
        int4 o;
        o.x = atomicAdd(&d_cnt[d.x], 1);
        o.y = atomicAdd(&d_cnt[d.y], 1);
        o.z = atomicAdd(&d_cnt[d.z], 1);
        o.w = atomicAdd(&d_cnt[d.w], 1);
        reinterpret_cast<int4*>(d_eoff)[i] = o;
    }
}

// Fused scan+emit, grid-resident (196 blocks all fit in wave 1):
//  - each block scans its 256 cnt values (read once) and zeroes cnt (self-clean)
//  - last-arriving block scans the 196 block sums, publishes d_boff + flag
//  - all blocks spin on the flag, then emit rowptr
//  - last-finishing block resets tickets/flag for the next graph replay
__global__ __launch_bounds__(SCAN_BS) void csr_scan_emit_kernel() {
    __shared__ int sh[SCAN_BS];
    __shared__ bool s_last;
    __shared__ int s_boff;
    int b = blockIdx.x, t = threadIdx.x;
    int i = b * SCAN_BS + t;
    int v = (i < NN) ? d_cnt[i] : 0;
    if (i < NN) d_cnt[i] = 0;        // self-clean for the next replay

    // Hillis-Steele inclusive scan of the block's 256 values
    sh[t] = v;
    __syncthreads();
    for (int d = 1; d < SCAN_BS; d <<= 1) {
        int x = sh[t];
        int add = (t >= d) ? sh[t - d] : 0;
        __syncthreads();
        sh[t] = x + add;
        __syncthreads();
    }
    int incl = sh[t];
    int total = sh[SCAN_BS - 1];

    volatile int* vflag = &d_scan_flag;
    if (t == 0) {
        d_bsum[b] = total;
        __threadfence();
        int ticket = atomicAdd(&d_scan_ctr, 1);
        s_last = (ticket == SCAN_NB - 1);
    }
    __syncthreads();

    if (s_last) {
        // this block scans the 196 block sums (needs sh[] again)
        __syncthreads();
        int x = (t < SCAN_NB) ? d_bsum[t] : 0;
        int orig = x;
        sh[t] = x;
        __syncthreads();
        for (int d = 1; d < SCAN_BS; d <<= 1) {
            int y = sh[t];
            int add = (t >= d) ? sh[t - d] : 0;
            __syncthreads();
            sh[t] = y + add;
            __syncthreads();
        }
        if (t < SCAN_NB) d_boff[t] = sh[t] - orig;   // exclusive
        if (t == SCAN_NB - 1) d_rowptr[NN] = sh[t];
        __threadfence();
        if (t == 0) *vflag = 1;
    }

    // wait for boff publication, then emit
    if (t == 0) {
        while (*vflag == 0) {}
        __threadfence();
        s_boff = d_boff[b];
    }
    __syncthreads();
    if (i < NN) d_rowptr[i] = s_boff + incl - v;    // exclusive prefix
    __syncthreads();
    if (t == 0) {
        int ticket2 = atomicAdd(&d_done_ctr, 1);
        if (ticket2 == SCAN_NB - 1) {   // all blocks done: reset state for next replay
            d_scan_flag = 0;
            d_scan_ctr = 0;
            d_done_ctr = 0;
        }
    }
}

// Atomic-free scatter: destination slot = rowptr[dst] + ticket.
// Pure data movement: coalesced LDG.128 streams, L2-resident rowptr gather,
// scattered 4B store. No dependent atomic latency chain.
__global__ void scatter_kernel(const int4* __restrict__ src4, const int4* __restrict__ dst4) {
    int i = blockIdx.x * blockDim.x + threadIdx.x;
    if (i < EE / 4) {
        int4 s = src4[i];
        int4 d = dst4[i];
        int4 o = reinterpret_cast<const int4*>(d_eoff)[i];
        int p0 = d_rowptr[d.x] + o.x;
        int p1 = d_rowptr[d.y] + o.y;
        int p2 = d_rowptr[d.z] + o.z;
        int p3 = d_rowptr[d.w] + o.w;
        d_esrc[p0] = s.x;
        d_esrc[p1] = s.y;
        d_esrc[p2] = s.z;
        d_esrc[p3] = s.w;
    }
}

// ---------------- tensor-core GEMM ----------------
__device__ __forceinline__ void mma16816(float* d,
                                         unsigned a0, unsigned a1, unsigned a2, unsigned a3,
                                         unsigned b0, unsigned b1) {
    asm volatile(
        "mma.sync.aligned.m16n8k16.row.col.f32.f16.f16.f32 "
        "{%0,%1,%2,%3}, {%4,%5,%6,%7}, {%8,%9}, {%0,%1,%2,%3};"
        : "+f"(d[0]), "+f"(d[1]), "+f"(d[2]), "+f"(d[3])
        : "r"(a0), "r"(a1), "r"(a2), "r"(a3), "r"(b0), "r"(b1));
}
__device__ __forceinline__ unsigned f2h2(float lo, float hi) {
    __half2 h = __floats2half2_rn(lo, hi);
    return *reinterpret_cast<unsigned*>(&h);
}

// ft = x @ W -> fp16 transposed [n][d*4+h], fused el/er (fp32), via HMMA m16n8k16.
// Block: 256 threads (8 warps), 128 rows/block, full N=128, K=128 (8 k-steps).
// __launch_bounds__(256, 2): cap regs at 128 so 2 CTAs fit per SM.
#define WSTRIDE 136
template <bool X_IS_HALF>
__global__ __launch_bounds__(256, 2) void gemm_tc_kernel(const float* __restrict__ xin,
                                                         const float* __restrict__ W,
                                                         const float* __restrict__ al,
                                                         const float* __restrict__ ar) {
    __shared__ __half Wt[128 * WSTRIDE];   // union: W^T fp16 [n][k], then per-warp staging
    __shared__ float sal[128], sar[128];
    int t = threadIdx.x;
    int w = t >> 5, l = t & 31;
    int g = l >> 2, tig = l & 3;
    int row0 = blockIdx.x * 128;

    // W fp32 [k][n] -> Wt fp16 [n][k] (coalesced global read)
#pragma unroll
    for (int i = 0; i < 64; i++) {
        int idx = t + 256 * i;
        int k = idx >> 7, n = idx & 127;
        Wt[n * WSTRIDE + k] = __float2half(W[idx]);
    }
    if (t < 128) sal[t] = al[t];
    else sar[t - 128] = ar[t - 128];
    __syncthreads();

    float acc[16][4];
#pragma unroll
    for (int nt = 0; nt < 16; nt++)
#pragma unroll
        for (int j = 0; j < 4; j++) acc[nt][j] = 0.f;

    int r1 = row0 + w * 16 + g;   // rows this thread's fragments cover
    int r2 = r1 + 8;
    bool ok1 = r1 < NN, ok2 = r2 < NN;

#pragma unroll
    for (int ks = 0; ks < 8; ks++) {
        int k0 = ks * 16 + 2 * tig;
        unsigned a0 = 0, a1 = 0, a2 = 0, a3 = 0;
        if (X_IS_HALF) {
            if (ok1) {
                a0 = *reinterpret_cast<const unsigned*>(&d_xh[r1 * 128 + k0]);
                a2 = *reinterpret_cast<const unsigned*>(&d_xh[r1 * 128 + k0 + 8]);
            }
            if (ok2) {
                a1 = *reinterpret_cast<const unsigned*>(&d_xh[r2 * 128 + k0]);
                a3 = *reinterpret_cast<const unsigned*>(&d_xh[r2 * 128 + k0 + 8]);
            }
        } else {
            if (ok1) {
                float2 f = *reinterpret_cast<const float2*>(&xin[r1 * 128 + k0]);
                a0 = f2h2(f.x, f.y);
                f = *reinterpret_cast<const float2*>(&xin[r1 * 128 + k0 + 8]);
                a2 = f2h2(f.x, f.y);
            }
            if (ok2) {
                float2 f = *reinterpret_cast<const float2*>(&xin[r2 * 128 + k0]);
                a1 = f2h2(f.x, f.y);
                f = *reinterpret_cast<const float2*>(&xin[r2 * 128 + k0 + 8]);
                a3 = f2h2(f.x, f.y);
            }
        }
#pragma unroll
        for (int nt = 0; nt < 16; nt++) {
            const __half* bp = &Wt[(nt * 8 + g) * WSTRIDE + k0];
            unsigned b0 = *reinterpret_cast<const unsigned*>(bp);
            unsigned b1 = *reinterpret_cast<const unsigned*>(bp + 8);
            mma16816(acc[nt], a0, a1, a2, a3, b0, b1);
        }
    }

    // fused el/er from fragments: col c = nt*8 + 2*tig (+1); head = nt>>2
    {
        float pll[4] = {0, 0, 0, 0}, plh[4] = {0, 0, 0, 0};
        float prl[4] = {0, 0, 0, 0}, prh[4] = {0, 0, 0, 0};
#pragma unroll
        for (int nt = 0; nt < 16; nt++) {
            int hh = nt >> 2;
            int c = nt * 8 + 2 * tig;
            float s0 = sal[c], s1 = sal[c + 1];
            float u0 = sar[c], u1 = sar[c + 1];
            pll[hh] += acc[nt][0] * s0 + acc[nt][1] * s1;
            plh[hh] += acc[nt][2] * s0 + acc[nt][3] * s1;
            prl[hh] += acc[nt][0] * u0 + acc[nt][1] * u1;
            prh[hh] += acc[nt][2] * u0 + acc[nt][3] * u1;
        }
#pragma unroll
        for (int o = 1; o <= 2; o <<= 1) {
#pragma unroll
            for (int hh = 0; hh < 4; hh++) {
                pll[hh] += __shfl_xor_sync(0xffffffffu, pll[hh], o);
                plh[hh] += __shfl_xor_sync(0xffffffffu, plh[hh], o);
                prl[hh] += __shfl_xor_sync(0xffffffffu, prl[hh], o);
                prh[hh] += __shfl_xor_sync(0xffffffffu, prh[hh], o);
            }
        }
        if (tig == 0) {
            if (ok1) {
                *reinterpret_cast<float4*>(&d_el[r1 * 4]) = make_float4(pll[0], pll[1], pll[2], pll[3]);
                *reinterpret_cast<float4*>(&d_er[r1 * 4]) = make_float4(prl[0], prl[1], prl[2], prl[3]);
            }
            if (ok2) {
                *reinterpret_cast<float4*>(&d_el[r2 * 4]) = make_float4(plh[0], plh[1], plh[2], plh[3]);
                *reinterpret_cast<float4*>(&d_er[r2 * 4]) = make_float4(prh[0], prh[1], prh[2], prh[3]);
            }
        }
    }

    // stage D (fp16) per warp, then write ft transposed [r][d*4+h]
    __syncthreads();   // all warps done reading Wt
    __half* stg = &Wt[w * 16 * WSTRIDE];
#pragma unroll
    for (int nt = 0; nt < 16; nt++) {
        int c = nt * 8 + 2 * tig;
        *reinterpret_cast<unsigned*>(&stg[g * WSTRIDE + c]) = f2h2(acc[nt][0], acc[nt][1]);
        *reinterpret_cast<unsigned*>(&stg[(g + 8) * WSTRIDE + c]) = f2h2(acc[nt][2], acc[nt][3]);
    }
    __syncwarp();
#pragma unroll
    for (int r = 0; r < 16; r++) {
        int rr = row0 + w * 16 + r;
        if (rr < NN) {
            __half v0 = stg[r * WSTRIDE + l];
            __half v1 = stg[r * WSTRIDE + 32 + l];
            __half v2 = stg[r * WSTRIDE + 64 + l];
            __half v3 = stg[r * WSTRIDE + 96 + l];
            __half2 p01 = __halves2half2(v0, v1);
            __half2 p23 = __halves2half2(v2, v3);
            uint2 o;
            o.x = *reinterpret_cast<unsigned*>(&p01);
            o.y = *reinterpret_cast<unsigned*>(&p23);
            *reinterpret_cast<uint2*>(&d_fth[rr * 128 + l * 4]) = o;
        }
    }
}

// ---------------- per-dst-node softmax + aggregation, single pass (no max) ----------------
// MODE 0: write ELU(result) as fp16 into d_xh ([n][h*32+d]). MODE 1: write mean over heads into out.
template <int MODE>
__global__ __launch_bounds__(256) void agg_kernel(const float* __restrict__ bias,
                                                  float* __restrict__ out) {
    __shared__ float4 sw[8][32];
    __shared__ int ss[8][32];
    int warp = threadIdx.x >> 5, lane = threadIdx.x & 31;
    int n = blockIdx.x * 8 + warp;
    if (n >= NN) return;
    int start = d_rowptr[n], end = d_rowptr[n + 1];
    float4 ern = *reinterpret_cast<const float4*>(&d_er[n * 4]);

    float acc0 = 0.f, acc1 = 0.f, acc2 = 0.f, acc3 = 0.f;
    float z0 = 0.f, z1 = 0.f, z2 = 0.f, z3 = 0.f;

    for (int c = start; c < end; c += 32) {
        int idx = c + lane;
        int s = 0;
        float4 w = make_float4(0.f, 0.f, 0.f, 0.f);
        if (idx < end) {
            s = d_esrc[idx];
            float4 e4 = *reinterpret_cast<const float4*>(&d_el[s * 4]);
            float e;
            e = e4.x + ern.x; e = e > 0.f ? e : 0.2f * e; w.x = __expf(e);
            e = e4.y + ern.y; e = e > 0.f ? e : 0.2f * e; w.y = __expf(e);
            e = e4.z + ern.z; e = e > 0.f ? e : 0.2f * e; w.z = __expf(e);
            e = e4.w + ern.w; e = e > 0.f ? e : 0.2f * e; w.w = __expf(e);
            z0 += w.x; z1 += w.y; z2 += w.z; z3 += w.w;
        }
        ss[warp][lane] = s;
        sw[warp][lane] = w;
        __syncwarp();
        int cnt = end - c; if (cnt > 32) cnt = 32;
        int j = 0;
        // 4-wide batches: 4 independent LDG.64 in flight before the FMAs
        for (; j + 4 <= cnt; j += 4) {
            int sa = ss[warp][j], sb = ss[warp][j + 1];
            int sc = ss[warp][j + 2], sd = ss[warp][j + 3];
            float4 wa = sw[warp][j], wb = sw[warp][j + 1];
            float4 wc = sw[warp][j + 2], wd = sw[warp][j + 3];
            uint2 fa = *reinterpret_cast<const uint2*>(&d_fth[sa * 128 + lane * 4]);
            uint2 fb = *reinterpret_cast<const uint2*>(&d_fth[sb * 128 + lane * 4]);
            uint2 fc = *reinterpret_cast<const uint2*>(&d_fth[sc * 128 + lane * 4]);
            uint2 fd = *reinterpret_cast<const uint2*>(&d_fth[sd * 128 + lane * 4]);
            float2 a01 = __half22float2(*reinterpret_cast<__half2*>(&fa.x));
            float2 a23 = __half22float2(*reinterpret_cast<__half2*>(&fa.y));
            float2 b01 = __half22float2(*reinterpret_cast<__half2*>(&fb.x));
            float2 b23 = __half22float2(*reinterpret_cast<__half2*>(&fb.y));
            float2 c01 = __half22float2(*reinterpret_cast<__half2*>(&fc.x));
            float2 c23 = __half22float2(*reinterpret_cast<__half2*>(&fc.y));
            float2 d01 = __half22float2(*reinterpret_cast<__half2*>(&fd.x));
            float2 d23 = __half22float2(*reinterpret_cast<__half2*>(&fd.y));
            acc0 += wa.x * a01.x; acc1 += wa.y * a01.y; acc2 += wa.z * a23.x; acc3 += wa.w * a23.y;
            acc0 += wb.x * b01.x; acc1 += wb.y * b01.y; acc2 += wb.z * b23.x; acc3 += wb.w * b23.y;
            acc0 += wc.x * c01.x; acc1 += wc.y * c01.y; acc2 += wc.z * c23.x; acc3 += wc.w * c23.y;
            acc0 += wd.x * d01.x; acc1 += wd.y * d01.y; acc2 += wd.z * d23.x; acc3 += wd.w * d23.y;
        }
        for (; j < cnt; j++) {
            int s2 = ss[warp][j];
            float4 wv = sw[warp][j];
            uint2 f = *reinterpret_cast<const uint2*>(&d_fth[s2 * 128 + lane * 4]);
            float2 f01 = __half22float2(*reinterpret_cast<__half2*>(&f.x));
            float2 f23 = __half22float2(*reinterpret_cast<__half2*>(&f.y));
            acc0 += wv.x * f01.x; acc1 += wv.y * f01.y;
            acc2 += wv.z * f23.x; acc3 += wv.w * f23.y;
        }
        __syncwarp();
    }
#pragma unroll
    for (int o = 16; o > 0; o >>= 1) {
        z0 += __shfl_xor_sync(0xffffffffu, z0, o);
        z1 += __shfl_xor_sync(0xffffffffu, z1, o);
        z2 += __shfl_xor_sync(0xffffffffu, z2, o);
        z3 += __shfl_xor_sync(0xffffffffu, z3, o);
    }

    float v0 = (z0 > 0.f ? acc0 / z0 : 0.f) + bias[0 * 32 + lane];
    float v1 = (z1 > 0.f ? acc1 / z1 : 0.f) + bias[1 * 32 + lane];
    float v2 = (z2 > 0.f ? acc2 / z2 : 0.f) + bias[2 * 32 + lane];
    float v3 = (z3 > 0.f ? acc3 / z3 : 0.f) + bias[3 * 32 + lane];

    if (MODE == 0) {
        v0 = v0 > 0.f ? v0 : __expf(v0) - 1.f;
        v1 = v1 > 0.f ? v1 : __expf(v1) - 1.f;
        v2 = v2 > 0.f ? v2 : __expf(v2) - 1.f;
        v3 = v3 > 0.f ? v3 : __expf(v3) - 1.f;
        d_xh[n * 128 + 0 * 32 + lane] = __float2half(v0);
        d_xh[n * 128 + 1 * 32 + lane] = __float2half(v1);
        d_xh[n * 128 + 2 * 32 + lane] = __float2half(v2);
        d_xh[n * 128 + 3 * 32 + lane] = __float2half(v3);
    } else {
        out[n * 32 + lane] = (v0 + v1 + v2 + v3) * 0.25f;
    }
}

// ---------------- launch ----------------
extern "C" void kernel_launch(void* const* d_in, const int* in_sizes, int n_in,
                              void* d_out, int out_size) {
    const float* h   = (const float*)d_in[0];
    const int*   src = (const int*)d_in[1];
    const int*   dst = (const int*)d_in[2];
    const float* W1  = (const float*)d_in[3];
    const float* al1 = (const float*)d_in[4];
    const float* ar1 = (const float*)d_in[5];
    const float* b1  = (const float*)d_in[6];
    const float* W2  = (const float*)d_in[7];
    const float* al2 = (const float*)d_in[8];
    const float* ar2 = (const float*)d_in[9];
    const float* b2  = (const float*)d_in[10];
    const float* W3  = (const float*)d_in[11];
    const float* al3 = (const float*)d_in[12];
    const float* ar3 = (const float*)d_in[13];
    const float* b3  = (const float*)d_in[14];
    float* out = (float*)d_out;

    const int GEMM_BLOCKS = (NN + 127) / 128;
    const int NODE_BLOCKS = (NN + 7) / 8;
    const int E4_BLOCKS = (EE / 4 + 255) / 256;

    // lazily-created side stream + events (created on first/correctness call,
    // reused for every call; no device-memory allocation involved)
    static cudaStream_t s2 = nullptr;
    static cudaEvent_t evFork = nullptr, evJoin = nullptr;
    if (s2 == nullptr) {
        cudaStreamCreateWithFlags(&s2, cudaStreamNonBlocking);
        cudaEventCreateWithFlags(&evFork, cudaEventDisableTiming);
        cudaEventCreateWithFlags(&evJoin, cudaEventDisableTiming);
    }

    // fork: layer-1 GEMM (independent of CSR build) runs on s2
    cudaEventRecord(evFork, 0);
    cudaStreamWaitEvent(s2, evFork, 0);
    gemm_tc_kernel<false><<<GEMM_BLOCKS, 256, 0, s2>>>(h, W1, al1, ar1);
    cudaEventRecord(evJoin, s2);

    // main stream: CSR build (reused by all 3 layers)
    // d_cnt is zero at entry (static init on first run; self-cleaned by
    // csr_scan_emit_kernel on every run) -> no memset launch needed.
    count_kernel<<<E4_BLOCKS, 256>>>((const int4*)dst);
    csr_scan_emit_kernel<<<SCAN_NB, SCAN_BS>>>();
    scatter_kernel<<<E4_BLOCKS, 256>>>((const int4*)src, (const int4*)dst);

    // join: agg1 needs both CSR and GEMM1 results
    cudaStreamWaitEvent(0, evJoin, 0);
    agg_kernel<0><<<NODE_BLOCKS, 256>>>(b1, nullptr);

    // layer 2
    gemm_tc_kernel<true><<<GEMM_BLOCKS, 256>>>(nullptr, W2, al2, ar2);
    agg_kernel<0><<<NODE_BLOCKS, 256>>>(b2, nullptr);

    // layer 3
    gemm_tc_kernel<true><<<GEMM_BLOCKS, 256>>>(nullptr, W3, al3, ar3);
    agg_kernel<1><<<NODE_BLOCKS, 256>>>(b3, out);
}